// round 2
// baseline (speedup 1.0000x reference)
#include <cuda_runtime.h>
#include <cuda_bf16.h>
#include <math.h>

#define NB 8
#define CIN 96
#define DIN 192
#define LQ 4096
#define SPQ 96

// ---------------- device scratch (zero-init BSS, no allocation) ----------------
__device__ float g_xz   [(long)NB*384*LQ];  // K1 out: ch 0..191 = xm, 192..383 = z-pre
__device__ float g_t    [(long)NB*384*LQ];  // z branch after 1x1 init conv
__device__ float g_t2   [(long)NB*384*LQ];  // after dw convs + gelu
__device__ float g_zf   [(long)NB*192*LQ];  // z branch final (NCHW, l=h*64+w)
__device__ float g_zsil [(long)NB*192*LQ];  // silu(zf) spatially transposed
__device__ float g_xc   [(long)NB*192*LQ];  // x branch after dw3x3+silu
__device__ float g_yL   [(long)NB*8*LQ];
__device__ float g_ym   [(long)NB*8*LQ];
__device__ float g_xdbl [(long)NB*22*LQ];
__device__ float g_xdbl2[(long)NB*22*LQ];
__device__ float g_delta[(long)NB*192*LQ];
__device__ float g_BC   [(long)NB*LQ*16];   // [b][l][Bs(8) Cs(8)]
__device__ float g_y    [(long)NB*192*LQ];
__device__ float g_yn   [(long)NB*192*LQ];
__device__ float g_A    [192*8];

__device__ float g_WinT  [96*384];
__device__ float g_Wd1T  [192*384];
__device__ float g_WdfT  [384*192];
__device__ float g_WxpT  [192*22];
__device__ float g_WoutT [192*96];

// ---------------- prep: transpose weights + materialize A ----------------
__global__ void prep_kernel(const float* __restrict__ Win, const float* __restrict__ Wd1,
                            const float* __restrict__ Wdf, const float* __restrict__ Wxp,
                            const float* __restrict__ Wout, const float* __restrict__ Alogs)
{
    int t = blockIdx.x * 256 + threadIdx.x;
    if (t < 384*96)  { int n = t/96,  k = t%96;  g_WinT[k*384 + n] = Win[t]; }
    if (t < 384*192) { int n = t/192, k = t%192; g_Wd1T[k*384 + n] = Wd1[t]; }
    if (t < 192*384) { int n = t/384, k = t%384; g_WdfT[k*192 + n] = Wdf[t]; }
    if (t < 22*192)  { int n = t/192, k = t%192; g_WxpT[k*22  + n] = Wxp[t]; }
    if (t < 96*192)  { int n = t/192, k = t%192; g_WoutT[k*96 + n] = Wout[t]; }
    if (t < 192*8)   g_A[t] = -expf(Alogs[t]);
}

// ---------------- generic fp32 GEMM: O[n][m] = bias[n] + sum_k A[k][m]*WT[k][n] ----------------
// A: per-batch channel-major, k-row stride = 4096 (=M). M fixed 4096. Tile 64x64x16, 128 threads.
__global__ void gemm_kernel(const float* __restrict__ A, long aStride,
                            const float* __restrict__ WT,
                            const float* __restrict__ bias,
                            float* __restrict__ O, long oStride,
                            int N, int K)
{
    __shared__ float sA[16][64];
    __shared__ float sW[16][64];
    const float* Ab = A + (long)blockIdx.z * aStride;
    float* Ob = O + (long)blockIdx.z * oStride;
    int m0 = blockIdx.x * 64, n0 = blockIdx.y * 64;
    int tid = threadIdx.x;
    int tm = tid & 15, tn = tid >> 4;
    float acc[8][4];
#pragma unroll
    for (int j = 0; j < 8; j++)
#pragma unroll
        for (int i = 0; i < 4; i++) acc[j][i] = 0.f;

    for (int kt = 0; kt < K; kt += 16) {
#pragma unroll
        for (int r = 0; r < 8; r++) {
            int e = tid + r * 128;
            int kk = e >> 6, mm = e & 63;
            sA[kk][mm] = Ab[(long)(kt + kk) * LQ + m0 + mm];
            int n = n0 + mm;
            sW[kk][mm] = (n < N) ? WT[(long)(kt + kk) * N + n] : 0.f;
        }
        __syncthreads();
#pragma unroll
        for (int kk = 0; kk < 16; kk++) {
            float av[4], bv[8];
#pragma unroll
            for (int i = 0; i < 4; i++) av[i] = sA[kk][tm * 4 + i];
#pragma unroll
            for (int j = 0; j < 8; j++) bv[j] = sW[kk][tn * 8 + j];
#pragma unroll
            for (int j = 0; j < 8; j++)
#pragma unroll
                for (int i = 0; i < 4; i++) acc[j][i] += av[i] * bv[j];
        }
        __syncthreads();
    }
#pragma unroll
    for (int j = 0; j < 8; j++) {
        int n = n0 + tn * 8 + j;
        if (n < N) {
            float bb = bias ? bias[n] : 0.f;
            float* orow = Ob + (long)n * LQ + m0 + tm * 4;
#pragma unroll
            for (int i = 0; i < 4; i++) orow[i] = acc[j][i] + bb;
        }
    }
}

// ---------------- z branch: multi-scale depthwise conv + exact GELU ----------------
__global__ void dwconvs_gelu_kernel(const float* __restrict__ W3, const float* __restrict__ b3,
                                    const float* __restrict__ W5, const float* __restrict__ b5,
                                    const float* __restrict__ W7, const float* __restrict__ b7)
{
    int l = blockIdx.x * 256 + threadIdx.x;
    int bc = blockIdx.y;
    int b = bc / 384, co = bc % 384;
    const float* tin = g_t + ((long)b * 384 + co) * LQ;
    float v;
    int h = l >> 6, w = l & 63;
    if (co < 96) {
        v = tin[l];
    } else {
        int ksz; const float* Wp; float bb;
        if (co < 192)      { ksz = 3; Wp = W3 + (co - 96) * 9;  bb = b3[co - 96]; }
        else if (co < 288) { ksz = 5; Wp = W5 + (co - 192) * 25; bb = b5[co - 192]; }
        else               { ksz = 7; Wp = W7 + (co - 288) * 49; bb = b7[co - 288]; }
        int pad = ksz >> 1;
        float acc = bb;
        for (int ky = 0; ky < ksz; ky++) {
            int y = h + ky - pad;
            if ((unsigned)y < 64u) {
                for (int kx = 0; kx < ksz; kx++) {
                    int x = w + kx - pad;
                    if ((unsigned)x < 64u) acc += tin[y * 64 + x] * Wp[ky * ksz + kx];
                }
            }
        }
        v = acc;
    }
    float g = 0.5f * v * (1.f + erff(v * 0.70710678118654752f));
    g_t2[((long)b * 384 + co) * LQ + l] = g;
}

// ---------------- zf spatial transpose + silu: zsil[b,d,h*64+w] = silu(zf[b,d,w*64+h]) -------
__global__ void ztrans_kernel()
{
    __shared__ float tile[32][33];
    long bd = blockIdx.z;
    int ti = blockIdx.y * 32, tj = blockIdx.x * 32;
    const float* src = g_zf + bd * LQ;
    float* dst = g_zsil + bd * LQ;
    int tx = threadIdx.x, ty = threadIdx.y;  // 32 x 8
#pragma unroll
    for (int r = 0; r < 32; r += 8)
        tile[ty + r][tx] = src[(ti + ty + r) * 64 + tj + tx];
    __syncthreads();
#pragma unroll
    for (int r = 0; r < 32; r += 8) {
        int a = ty + r;
        float v = tile[tx][a];
        dst[(tj + a) * 64 + ti + tx] = v / (1.f + __expf(-v));
    }
}

// ---------------- x branch: depthwise 3x3 + bias + silu ----------------
__global__ void dw3_silu_kernel(const float* __restrict__ W, const float* __restrict__ bias)
{
    int l = blockIdx.x * 256 + threadIdx.x;
    int bc = blockIdx.y;
    int b = bc / 192, c = bc % 192;
    const float* src = g_xz + ((long)b * 384 + c) * LQ;  // xm = channels 0..191
    int h = l >> 6, w = l & 63;
    float acc = bias[c];
    const float* wp = W + c * 9;
#pragma unroll
    for (int ky = 0; ky < 3; ky++) {
        int y = h + ky - 1;
        if ((unsigned)y < 64u) {
#pragma unroll
            for (int kx = 0; kx < 3; kx++) {
                int x = w + kx - 1;
                if ((unsigned)x < 64u) acc += src[y * 64 + x] * wp[ky * 3 + kx];
            }
        }
    }
    g_xc[((long)b * 192 + c) * LQ + l] = acc / (1.f + __expf(-acc));
}

// ---------------- haar 1x1 conv + strided combine -> yL, y_mean ----------------
// block = (i, b); i in 0..31 (output row), 256 threads.
__global__ void haar_kernel(const float* __restrict__ Wh)
{
    extern __shared__ float sm[];
    float* sW = sm;               // 32*192
    float* s1 = sm + 32 * 192;    // 192*32
    float* s2 = s1 + 192 * 32;    // 192*32
    int i = blockIdx.x, b = blockIdx.y;
    int tid = threadIdx.x;
    for (int e = tid; e < 32 * 192; e += 256) sW[e] = Wh[e];
    const float* xcb = g_xc + (long)b * 192 * LQ;
    for (int e = tid; e < 192 * 32; e += 256) {
        int d = e >> 5, j = e & 31;
        const float* row0 = xcb + (long)d * LQ + (2 * i) * 64 + 2 * j;
        float xa = row0[0], xb = row0[1];
        float xc2 = row0[64], xd = row0[65];
        s1[d * 32 + j] = xa + xb + xc2 + xd;
        s2[d * 32 + j] = 3.f * xa - xb - xc2 - xd;
    }
    __syncthreads();
    for (int e = tid; e < 2048; e += 256) {
        int which = e >> 10;
        int ch = (e >> 5) & 31;
        int j = e & 31;
        const float* sv = (which ? s2 : s1) + j;
        const float* wr = sW + ch * 192;
        float acc = 0.f;
#pragma unroll 4
        for (int d = 0; d < 192; d++) acc += wr[d] * sv[d * 32];
        acc *= which ? (1.f / 6.f) : 0.5f;
        int n = ch >> 2;
        int lpos = (ch & 3) * 1024 + i * 32 + j;
        float* dst = which ? g_ym : g_yL;
        dst[((long)b * 8 + n) * LQ + lpos] = acc;
    }
}

// ---------------- depthwise conv1d k=7 pad=3 along l ----------------
__global__ void conv1d_kernel(const float* __restrict__ Wx, const float* __restrict__ bx)
{
    int l = blockIdx.x * 256 + threadIdx.x;
    int bc = blockIdx.y;
    int b = bc / 22, c = bc % 22;
    const float* src = g_xdbl + ((long)b * 22 + c) * LQ;
    float acc = bx[c];
#pragma unroll
    for (int k = 0; k < 7; k++) {
        int ll = l + k - 3;
        if ((unsigned)ll < (unsigned)LQ) acc += src[ll] * Wx[c * 7 + k];
    }
    g_xdbl2[((long)b * 22 + c) * LQ + l] = acc;
}

// ---------------- dt projection (K=6 -> 192) + softplus ----------------
__global__ void dtproj_kernel(const float* __restrict__ Wdt, const float* __restrict__ dtb)
{
    __shared__ float sW[192 * 6];
    __shared__ float sB[192];
    int tid = threadIdx.x;
    for (int e = tid; e < 1152; e += 256) sW[e] = Wdt[e];
    for (int e = tid; e < 192; e += 256) sB[e] = dtb[e];
    __syncthreads();
    int l = blockIdx.x * 256 + tid;
    int b = blockIdx.y;
    float r[6];
#pragma unroll
    for (int rr = 0; rr < 6; rr++) r[rr] = g_xdbl2[((long)b * 22 + rr) * LQ + l];
    float* dout = g_delta + (long)b * 192 * LQ + l;
    for (int d = 0; d < 192; d++) {
        float s = sB[d];
#pragma unroll
        for (int rr = 0; rr < 6; rr++) s += sW[d * 6 + rr] * r[rr];
        float sp = (s > 20.f) ? s : log1pf(expf(s));
        dout[(long)d * LQ] = sp;
    }
}

// ---------------- B/C assembly into [b][l][16] ----------------
__global__ void bc_kernel()
{
    int l = blockIdx.x * 256 + threadIdx.x;
    int b = blockIdx.y;
    float* o = g_BC + ((long)b * LQ + l) * 16;
#pragma unroll
    for (int n = 0; n < 8; n++) {
        float bs = g_xdbl2[((long)b * 22 + 6 + n) * LQ + l]  * g_yL[((long)b * 8 + n) * LQ + l] + 1e-6f;
        float cs = g_xdbl2[((long)b * 22 + 14 + n) * LQ + l] * g_ym[((long)b * 8 + n) * LQ + l] + 1e-6f;
        o[n] = bs;
        o[8 + n] = cs;
    }
}

// ---------------- selective scan: block per (b,d), two-pass chunked scan ----------------
__global__ void scan_kernel(const float* __restrict__ Ds)
{
    extern __shared__ float sm[];
    float* sDelta = sm;          // 4096
    float* sU = sm + 4096;       // 4096
    float* sScan = sm + 8192;    // 4096 (A:2048 | B:2048) then reused as Y
    int bd = blockIdx.x;
    int b = bd / 192, d = bd % 192;
    int tid = threadIdx.x;
    const float* dp = g_delta + ((long)b * 192 + d) * LQ;
    const float* up = g_xc    + ((long)b * 192 + d) * LQ;
    for (int e = tid; e < LQ; e += 256) { sDelta[e] = dp[e]; sU[e] = up[e]; }
    float An[8];
#pragma unroll
    for (int n = 0; n < 8; n++) An[n] = g_A[d * 8 + n];
    __syncthreads();
    const float* bc = g_BC + (long)b * LQ * 16;

    // pass 1: per-thread chunk transform (a, h) with h_in = 0
    float a[8], hh[8];
#pragma unroll
    for (int n = 0; n < 8; n++) { a[n] = 1.f; hh[n] = 0.f; }
    int base = tid * 16;
    for (int i = 0; i < 16; i++) {
        int l = base + i;
        float delta = sDelta[l];
        float du = delta * sU[l];
        const float* bcl = bc + (long)l * 16;
#pragma unroll
        for (int n = 0; n < 8; n++) {
            float p = __expf(delta * An[n]);
            hh[n] = p * hh[n] + du * bcl[n];
            a[n] *= p;
        }
    }
#pragma unroll
    for (int n = 0; n < 8; n++) { sScan[n * 256 + tid] = a[n]; sScan[2048 + n * 256 + tid] = hh[n]; }
    __syncthreads();

    // inclusive Hillis-Steele scan over 256 chunk transforms
    for (int off = 1; off < 256; off <<= 1) {
        float pa[8], pb[8];
        if (tid >= off) {
#pragma unroll
            for (int n = 0; n < 8; n++) {
                pa[n] = sScan[n * 256 + tid - off];
                pb[n] = sScan[2048 + n * 256 + tid - off];
            }
        }
        __syncthreads();
        if (tid >= off) {
#pragma unroll
            for (int n = 0; n < 8; n++) {
                float a2 = sScan[n * 256 + tid];
                float b2 = sScan[2048 + n * 256 + tid];
                sScan[n * 256 + tid] = pa[n] * a2;
                sScan[2048 + n * 256 + tid] = a2 * pb[n] + b2;
            }
        }
        __syncthreads();
    }
    float h0[8];
#pragma unroll
    for (int n = 0; n < 8; n++) h0[n] = (tid == 0) ? 0.f : sScan[2048 + n * 256 + tid - 1];
    __syncthreads();  // before reusing sScan as Y buffer

    // pass 2: recompute with correct h_init, emit y
    float Dd = Ds[d];
    for (int i = 0; i < 16; i++) {
        int l = base + i;
        float delta = sDelta[l];
        float u = sU[l];
        float du = delta * u;
        const float* bcl = bc + (long)l * 16;
        float y = Dd * u;
#pragma unroll
        for (int n = 0; n < 8; n++) {
            float p = __expf(delta * An[n]);
            h0[n] = p * h0[n] + du * bcl[n];
            y += h0[n] * bcl[8 + n];
        }
        sScan[l] = y;
    }
    __syncthreads();
    float* yo = g_y + ((long)b * 192 + d) * LQ;
    for (int e = tid; e < LQ; e += 256) yo[e] = sScan[e];
}

// ---------------- LayerNorm over d + silu(z) gate ----------------
__global__ void ln_kernel(const float* __restrict__ gamma, const float* __restrict__ beta)
{
    __shared__ float sg[192], sb2[192];
    int tid = threadIdx.x;
    for (int e = tid; e < 192; e += 256) { sg[e] = gamma[e]; sb2[e] = beta[e]; }
    __syncthreads();
    int l = blockIdx.x * 256 + tid;
    int b = blockIdx.y;
    const float* yp = g_y + (long)b * 192 * LQ + l;
    float s = 0.f, ss = 0.f;
    for (int dd = 0; dd < 192; dd++) {
        float v = yp[(long)dd * LQ];
        s += v; ss += v * v;
    }
    float mu = s * (1.f / 192.f);
    float var = ss * (1.f / 192.f) - mu * mu;
    float rs = rsqrtf(var + 1e-5f);
    const float* zp = g_zsil + (long)b * 192 * LQ + l;
    float* op = g_yn + (long)b * 192 * LQ + l;
    for (int dd = 0; dd < 192; dd++) {
        float v = (yp[(long)dd * LQ] - mu) * rs * sg[dd] + sb2[dd];
        op[(long)dd * LQ] = v * zp[(long)dd * LQ];
    }
}

// ---------------- host launcher ----------------
extern "C" void kernel_launch(void* const* d_in, const int* in_sizes, int n_in,
                              void* d_out, int out_size)
{
    const float* x        = (const float*)d_in[0];
    const float* W_in     = (const float*)d_in[1];
    const float* W_dwc_i  = (const float*)d_in[2];
    const float* b_dwc_i  = (const float*)d_in[3];
    const float* W_dw3    = (const float*)d_in[4];
    const float* b_dw3    = (const float*)d_in[5];
    const float* W_dw5    = (const float*)d_in[6];
    const float* b_dw5    = (const float*)d_in[7];
    const float* W_dw7    = (const float*)d_in[8];
    const float* b_dw7    = (const float*)d_in[9];
    const float* W_dwc_f  = (const float*)d_in[10];
    const float* b_dwc_f  = (const float*)d_in[11];
    const float* W_conv2d = (const float*)d_in[12];
    const float* b_conv2d = (const float*)d_in[13];
    const float* W_haar   = (const float*)d_in[14];
    const float* x_proj_w = (const float*)d_in[15];
    const float* W_xconv  = (const float*)d_in[16];
    const float* b_xconv  = (const float*)d_in[17];
    const float* dt_w     = (const float*)d_in[18];
    const float* dt_b     = (const float*)d_in[19];
    const float* A_logs   = (const float*)d_in[20];
    const float* Ds       = (const float*)d_in[21];
    const float* ln_g     = (const float*)d_in[22];
    const float* ln_b     = (const float*)d_in[23];
    const float* W_out    = (const float*)d_in[24];
    float* out = (float*)d_out;

    float *p_xz, *p_t, *p_t2, *p_zf, *p_xc, *p_xdbl, *p_yn;
    float *p_WinT, *p_Wd1T, *p_WdfT, *p_WxpT, *p_WoutT;
    cudaGetSymbolAddress((void**)&p_xz, g_xz);
    cudaGetSymbolAddress((void**)&p_t, g_t);
    cudaGetSymbolAddress((void**)&p_t2, g_t2);
    cudaGetSymbolAddress((void**)&p_zf, g_zf);
    cudaGetSymbolAddress((void**)&p_xc, g_xc);
    cudaGetSymbolAddress((void**)&p_xdbl, g_xdbl);
    cudaGetSymbolAddress((void**)&p_yn, g_yn);
    cudaGetSymbolAddress((void**)&p_WinT, g_WinT);
    cudaGetSymbolAddress((void**)&p_Wd1T, g_Wd1T);
    cudaGetSymbolAddress((void**)&p_WdfT, g_WdfT);
    cudaGetSymbolAddress((void**)&p_WxpT, g_WxpT);
    cudaGetSymbolAddress((void**)&p_WoutT, g_WoutT);

    cudaFuncSetAttribute(haar_kernel, cudaFuncAttributeMaxDynamicSharedMemorySize, 73728);
    cudaFuncSetAttribute(scan_kernel, cudaFuncAttributeMaxDynamicSharedMemorySize, 49152);

    // prep: weight transposes + A
    prep_kernel<<<288, 256>>>(W_in, W_dwc_i, W_dwc_f, x_proj_w, W_out, A_logs);

    // K1: input GEMM  x[b,96,L] -> xz[b,384,L]
    gemm_kernel<<<dim3(64, 6, NB), 128>>>(x, 96L * LQ, p_WinT, nullptr,
                                          p_xz, 384L * LQ, 384, 96);
    // K2: z branch 1x1 init conv (K=192 -> 384)
    gemm_kernel<<<dim3(64, 6, NB), 128>>>(p_xz + 192L * LQ, 384L * LQ, p_Wd1T, b_dwc_i,
                                          p_t, 384L * LQ, 384, 192);
    // K3: multi-scale depthwise + gelu
    dwconvs_gelu_kernel<<<dim3(16, NB * 384), 256>>>(W_dw3, b_dw3, W_dw5, b_dw5, W_dw7, b_dw7);
    // K4: z branch final 1x1 conv (K=384 -> 192)
    gemm_kernel<<<dim3(64, 3, NB), 128>>>(p_t2, 384L * LQ, p_WdfT, b_dwc_f,
                                          p_zf, 192L * LQ, 192, 384);
    // K4b: transpose + silu gate
    ztrans_kernel<<<dim3(2, 2, NB * 192), dim3(32, 8)>>>();
    // K5: x branch depthwise 3x3 + silu
    dw3_silu_kernel<<<dim3(16, NB * 192), 256>>>(W_conv2d, b_conv2d);
    // K6: haar -> yL, y_mean
    haar_kernel<<<dim3(32, NB), 256, 73728>>>(W_haar);
    // K7a: x_proj GEMM (K=192 -> 22)
    gemm_kernel<<<dim3(64, 1, NB), 128>>>(p_xc, 192L * LQ, p_WxpT, nullptr,
                                          p_xdbl, 22L * LQ, 22, 192);
    // K7b: depthwise conv1d k=7
    conv1d_kernel<<<dim3(16, NB * 22), 256>>>(W_xconv, b_xconv);
    // K7c: dt projection + softplus
    dtproj_kernel<<<dim3(16, NB), 256>>>(dt_w, dt_b);
    // K7d: Bs/Cs assembly
    bc_kernel<<<dim3(16, NB), 256>>>();
    // K8: selective scan
    scan_kernel<<<NB * 192, 256, 49152>>>(Ds);
    // K9a: layernorm + gate
    ln_kernel<<<dim3(16, NB), 256>>>(ln_g, ln_b);
    // K9b: output GEMM (K=192 -> 96) straight into d_out
    gemm_kernel<<<dim3(64, 2, NB), 128>>>(p_yn, 192L * LQ, p_WoutT, nullptr,
                                          out, 96L * LQ, 96, 192);
    (void)in_sizes; (void)n_in; (void)out_size;
}

// round 3
// speedup vs baseline: 1.4534x; 1.4534x over previous
#include <cuda_runtime.h>
#include <cuda_bf16.h>
#include <math.h>

#define NB 8
#define LQ 4096

// ---------------- device scratch (zero-init BSS, no allocation) ----------------
__device__ float g_xz   [(long)NB*384*LQ];
__device__ float g_t    [(long)NB*384*LQ];
__device__ float g_t2   [(long)NB*384*LQ];
__device__ float g_zf   [(long)NB*192*LQ];
__device__ float g_zsil [(long)NB*192*LQ];
__device__ float g_xc   [(long)NB*192*LQ];
__device__ float g_yL   [(long)NB*8*LQ];
__device__ float g_ym   [(long)NB*8*LQ];
__device__ float g_xdbl [(long)NB*22*LQ];
__device__ float g_xdbl2[(long)NB*22*LQ];
__device__ float g_delta[(long)NB*192*LQ];
__device__ float g_BC   [(long)NB*LQ*16];
__device__ float g_y    [(long)NB*192*LQ];
__device__ float g_yn   [(long)NB*192*LQ];
__device__ float g_A    [192*8];

__device__ float g_WinT  [96*384];
__device__ float g_Wd1T  [192*384];
__device__ float g_WdfT  [384*192];
__device__ float g_WxpT  [192*22];
__device__ float g_WoutT [192*96];

// ---------------- prep: transpose weights + materialize A ----------------
__global__ void prep_kernel(const float* __restrict__ Win, const float* __restrict__ Wd1,
                            const float* __restrict__ Wdf, const float* __restrict__ Wxp,
                            const float* __restrict__ Wout, const float* __restrict__ Alogs)
{
    int t = blockIdx.x * 256 + threadIdx.x;
    if (t < 384*96)  { int n = t/96,  k = t%96;  g_WinT[k*384 + n] = Win[t]; }
    if (t < 384*192) { int n = t/192, k = t%192; g_Wd1T[k*384 + n] = Wd1[t]; }
    if (t < 192*384) { int n = t/384, k = t%384; g_WdfT[k*192 + n] = Wdf[t]; }
    if (t < 22*192)  { int n = t/192, k = t%192; g_WxpT[k*22  + n] = Wxp[t]; }
    if (t < 96*192)  { int n = t/192, k = t%192; g_WoutT[k*96 + n] = Wout[t]; }
    if (t < 192*8)   g_A[t] = -expf(Alogs[t]);
}

// ---------------- big-tile fp32 GEMM: O[n][m] = bias[n] + sum_k A[k][m]*WT[k][n] ---------
// Tile: M=128, N=64, K=16. 128 threads, 8x8 register tile, float4 loads, double-buffered.
__global__ void __launch_bounds__(128, 4)
gemm128_kernel(const float* __restrict__ A, long aStride,
               const float* __restrict__ WT,
               const float* __restrict__ bias,
               float* __restrict__ O, long oStride,
               int N, int K)
{
    __shared__ float sA[2][16][128];
    __shared__ float sW[2][16][64];
    const float* Ab = A + (long)blockIdx.z * aStride;
    float* Ob = O + (long)blockIdx.z * oStride;
    int m0 = blockIdx.x * 128, n0 = blockIdx.y * 64;
    int tid = threadIdx.x;
    int tm = tid & 15, tn = tid >> 4;

    int arow = tid >> 5;          // 0..3, rows arow+4r
    int acol = (tid & 31) * 4;    // float4 column

    float acc[8][8];
#pragma unroll
    for (int j = 0; j < 8; j++)
#pragma unroll
        for (int i = 0; i < 8; i++) acc[j][i] = 0.f;

    // preload tile 0
    {
#pragma unroll
        for (int r = 0; r < 4; r++) {
            int kk = arow + 4 * r;
            float4 v = *(const float4*)(Ab + (long)kk * LQ + m0 + acol);
            *(float4*)&sA[0][kk][acol] = v;
        }
#pragma unroll
        for (int r = 0; r < 8; r++) {
            int e = tid + r * 128;
            int kk = e >> 6, mm = e & 63;
            int n = n0 + mm;
            sW[0][kk][mm] = (n < N) ? WT[(long)kk * N + n] : 0.f;
        }
    }
    __syncthreads();

    int nTiles = K >> 4;
    for (int kt = 0; kt < nTiles; kt++) {
        int cur = kt & 1, nxt = cur ^ 1;
        float4 pA[4];
        float pW[8];
        bool hasNext = (kt + 1 < nTiles);
        if (hasNext) {
            int kb = (kt + 1) << 4;
#pragma unroll
            for (int r = 0; r < 4; r++) {
                int kk = arow + 4 * r;
                pA[r] = *(const float4*)(Ab + (long)(kb + kk) * LQ + m0 + acol);
            }
#pragma unroll
            for (int r = 0; r < 8; r++) {
                int e = tid + r * 128;
                int kk = e >> 6, mm = e & 63;
                int n = n0 + mm;
                pW[r] = (n < N) ? WT[(long)(kb + kk) * N + n] : 0.f;
            }
        }
#pragma unroll
        for (int kk = 0; kk < 16; kk++) {
            float4 a0 = *(const float4*)&sA[cur][kk][tm * 8];
            float4 a1 = *(const float4*)&sA[cur][kk][tm * 8 + 4];
            float4 b0 = *(const float4*)&sW[cur][kk][tn * 8];
            float4 b1 = *(const float4*)&sW[cur][kk][tn * 8 + 4];
            float av[8] = {a0.x,a0.y,a0.z,a0.w,a1.x,a1.y,a1.z,a1.w};
            float bv[8] = {b0.x,b0.y,b0.z,b0.w,b1.x,b1.y,b1.z,b1.w};
#pragma unroll
            for (int j = 0; j < 8; j++)
#pragma unroll
                for (int i = 0; i < 8; i++) acc[j][i] += av[i] * bv[j];
        }
        if (hasNext) {
#pragma unroll
            for (int r = 0; r < 4; r++) {
                int kk = arow + 4 * r;
                *(float4*)&sA[nxt][kk][acol] = pA[r];
            }
#pragma unroll
            for (int r = 0; r < 8; r++) {
                int e = tid + r * 128;
                int kk = e >> 6, mm = e & 63;
                sW[nxt][kk][mm] = pW[r];
            }
        }
        __syncthreads();
    }

#pragma unroll
    for (int j = 0; j < 8; j++) {
        int n = n0 + tn * 8 + j;
        if (n < N) {
            float bb = bias ? bias[n] : 0.f;
            float* orow = Ob + (long)n * LQ + m0 + tm * 8;
            float4 v0 = make_float4(acc[j][0]+bb, acc[j][1]+bb, acc[j][2]+bb, acc[j][3]+bb);
            float4 v1 = make_float4(acc[j][4]+bb, acc[j][5]+bb, acc[j][6]+bb, acc[j][7]+bb);
            *(float4*)orow = v0;
            *(float4*)(orow + 4) = v1;
        }
    }
}

// ---------------- small-N fp32 GEMM (kept for N=22) ----------------
__global__ void gemm_kernel(const float* __restrict__ A, long aStride,
                            const float* __restrict__ WT,
                            const float* __restrict__ bias,
                            float* __restrict__ O, long oStride,
                            int N, int K)
{
    __shared__ float sA[16][64];
    __shared__ float sW[16][64];
    const float* Ab = A + (long)blockIdx.z * aStride;
    float* Ob = O + (long)blockIdx.z * oStride;
    int m0 = blockIdx.x * 64, n0 = blockIdx.y * 64;
    int tid = threadIdx.x;
    int tm = tid & 15, tn = tid >> 4;
    float acc[8][4];
#pragma unroll
    for (int j = 0; j < 8; j++)
#pragma unroll
        for (int i = 0; i < 4; i++) acc[j][i] = 0.f;

    for (int kt = 0; kt < K; kt += 16) {
#pragma unroll
        for (int r = 0; r < 8; r++) {
            int e = tid + r * 128;
            int kk = e >> 6, mm = e & 63;
            sA[kk][mm] = Ab[(long)(kt + kk) * LQ + m0 + mm];
            int n = n0 + mm;
            sW[kk][mm] = (n < N) ? WT[(long)(kt + kk) * N + n] : 0.f;
        }
        __syncthreads();
#pragma unroll
        for (int kk = 0; kk < 16; kk++) {
            float av[4], bv[8];
#pragma unroll
            for (int i = 0; i < 4; i++) av[i] = sA[kk][tm * 4 + i];
#pragma unroll
            for (int j = 0; j < 8; j++) bv[j] = sW[kk][tn * 8 + j];
#pragma unroll
            for (int j = 0; j < 8; j++)
#pragma unroll
                for (int i = 0; i < 4; i++) acc[j][i] += av[i] * bv[j];
        }
        __syncthreads();
    }
#pragma unroll
    for (int j = 0; j < 8; j++) {
        int n = n0 + tn * 8 + j;
        if (n < N) {
            float bb = bias ? bias[n] : 0.f;
            float* orow = Ob + (long)n * LQ + m0 + tm * 4;
#pragma unroll
            for (int i = 0; i < 4; i++) orow[i] = acc[j][i] + bb;
        }
    }
}

// ---------------- z branch: smem-tiled depthwise conv (templated ksize) + exact GELU ----
__device__ __forceinline__ float gelu_exact(float v)
{
    return 0.5f * v * (1.f + erff(v * 0.70710678118654752f));
}

template<int KSZ>
__global__ void dwconv_gelu_kernel(const float* __restrict__ W, const float* __restrict__ bias,
                                   int coBase)
{
    constexpr int PAD = KSZ / 2;
    constexpr int SH = 64 + 2 * PAD;
    __shared__ float sm[SH * 72];
    int c = blockIdx.x;           // 0..95
    int b = blockIdx.y;
    int co = coBase + c;
    int tid = threadIdx.x;        // 256
    const float* src = g_t + ((long)b * 384 + co) * LQ;

    // zero the halo-padded tile, then fill interior
    for (int e = tid; e < SH * 72; e += 256) sm[e] = 0.f;
    __syncthreads();
    for (int e = tid; e < LQ; e += 256) {
        int h = e >> 6, w = e & 63;
        sm[(h + PAD) * 72 + (w + PAD)] = src[e];
    }
    __syncthreads();

    float wreg[KSZ * KSZ];
#pragma unroll
    for (int i = 0; i < KSZ * KSZ; i++) wreg[i] = W[c * KSZ * KSZ + i];
    float bb = bias[c];

    float* dst = g_t2 + ((long)b * 384 + co) * LQ;
    for (int e = tid; e < LQ; e += 256) {
        int h = e >> 6, w = e & 63;
        float acc = bb;
#pragma unroll
        for (int ky = 0; ky < KSZ; ky++) {
            const float* row = sm + (h + ky) * 72 + w;
#pragma unroll
            for (int kx = 0; kx < KSZ; kx++)
                acc += row[kx] * wreg[ky * KSZ + kx];
        }
        dst[e] = gelu_exact(acc);
    }
}

// gelu pass-through for channels [0,96)
__global__ void gelu_copy_kernel()
{
    long idx = (long)blockIdx.x * 256 + threadIdx.x;   // over NB*96*LQ
    int b = (int)(idx / (96L * LQ));
    long rem = idx - (long)b * 96 * LQ;
    int c = (int)(rem / LQ);
    int l = (int)(rem - (long)c * LQ);
    long off = ((long)b * 384 + c) * LQ + l;
    g_t2[off] = gelu_exact(g_t[off]);
}

// ---------------- zf spatial transpose + silu ----------------
__global__ void ztrans_kernel()
{
    __shared__ float tile[32][33];
    long bd = blockIdx.z;
    int ti = blockIdx.y * 32, tj = blockIdx.x * 32;
    const float* src = g_zf + bd * LQ;
    float* dst = g_zsil + bd * LQ;
    int tx = threadIdx.x, ty = threadIdx.y;  // 32 x 8
#pragma unroll
    for (int r = 0; r < 32; r += 8)
        tile[ty + r][tx] = src[(ti + ty + r) * 64 + tj + tx];
    __syncthreads();
#pragma unroll
    for (int r = 0; r < 32; r += 8) {
        int a = ty + r;
        float v = tile[tx][a];
        dst[(tj + a) * 64 + ti + tx] = v / (1.f + __expf(-v));
    }
}

// ---------------- x branch: depthwise 3x3 + bias + silu (smem tiled) ----------------
__global__ void dw3_silu_kernel(const float* __restrict__ W, const float* __restrict__ bias)
{
    __shared__ float sm[66 * 68];
    int c = blockIdx.x;     // 0..191
    int b = blockIdx.y;
    int tid = threadIdx.x;  // 256
    const float* src = g_xz + ((long)b * 384 + c) * LQ;  // xm channels 0..191
    for (int e = tid; e < 66 * 68; e += 256) sm[e] = 0.f;
    __syncthreads();
    for (int e = tid; e < LQ; e += 256) {
        int h = e >> 6, w = e & 63;
        sm[(h + 1) * 68 + (w + 1)] = src[e];
    }
    __syncthreads();
    float w0 = W[c*9+0], w1 = W[c*9+1], w2 = W[c*9+2];
    float w3 = W[c*9+3], w4 = W[c*9+4], w5 = W[c*9+5];
    float w6 = W[c*9+6], w7 = W[c*9+7], w8 = W[c*9+8];
    float bb = bias[c];
    float* dst = g_xc + ((long)b * 192 + c) * LQ;
    for (int e = tid; e < LQ; e += 256) {
        int h = e >> 6, w = e & 63;
        const float* r0 = sm + h * 68 + w;
        float acc = bb + r0[0]*w0 + r0[1]*w1 + r0[2]*w2
                       + r0[68]*w3 + r0[69]*w4 + r0[70]*w5
                       + r0[136]*w6 + r0[137]*w7 + r0[138]*w8;
        dst[e] = acc / (1.f + __expf(-acc));
    }
}

// ---------------- haar 1x1 conv + strided combine -> yL, y_mean ----------------
__global__ void haar_kernel(const float* __restrict__ Wh)
{
    extern __shared__ float smh[];
    float* sW = smh;              // 32*192
    float* s1 = smh + 32 * 192;   // 192*32
    float* s2 = s1 + 192 * 32;    // 192*32
    int i = blockIdx.x, b = blockIdx.y;
    int tid = threadIdx.x;
    for (int e = tid; e < 32 * 192; e += 256) sW[e] = Wh[e];
    const float* xcb = g_xc + (long)b * 192 * LQ;
    for (int e = tid; e < 192 * 32; e += 256) {
        int d = e >> 5, j = e & 31;
        const float* row0 = xcb + (long)d * LQ + (2 * i) * 64 + 2 * j;
        float xa = row0[0], xb = row0[1];
        float xc2 = row0[64], xd = row0[65];
        s1[d * 32 + j] = xa + xb + xc2 + xd;
        s2[d * 32 + j] = 3.f * xa - xb - xc2 - xd;
    }
    __syncthreads();
    for (int e = tid; e < 2048; e += 256) {
        int which = e >> 10;
        int ch = (e >> 5) & 31;
        int j = e & 31;
        const float* sv = (which ? s2 : s1) + j;
        const float* wr = sW + ch * 192;
        float acc = 0.f;
#pragma unroll 4
        for (int d = 0; d < 192; d++) acc += wr[d] * sv[d * 32];
        acc *= which ? (1.f / 6.f) : 0.5f;
        int n = ch >> 2;
        int lpos = (ch & 3) * 1024 + i * 32 + j;
        float* dst = which ? g_ym : g_yL;
        dst[((long)b * 8 + n) * LQ + lpos] = acc;
    }
}

// ---------------- depthwise conv1d k=7 pad=3 along l ----------------
__global__ void conv1d_kernel(const float* __restrict__ Wx, const float* __restrict__ bx)
{
    int l = blockIdx.x * 256 + threadIdx.x;
    int bc = blockIdx.y;
    int b = bc / 22, c = bc % 22;
    const float* src = g_xdbl + ((long)b * 22 + c) * LQ;
    float acc = bx[c];
#pragma unroll
    for (int k = 0; k < 7; k++) {
        int ll = l + k - 3;
        if ((unsigned)ll < (unsigned)LQ) acc += src[ll] * Wx[c * 7 + k];
    }
    g_xdbl2[((long)b * 22 + c) * LQ + l] = acc;
}

// ---------------- dt projection (K=6 -> 192) + softplus ----------------
__global__ void dtproj_kernel(const float* __restrict__ Wdt, const float* __restrict__ dtb)
{
    __shared__ float sW[192 * 6];
    __shared__ float sB[192];
    int tid = threadIdx.x;
    for (int e = tid; e < 1152; e += 256) sW[e] = Wdt[e];
    for (int e = tid; e < 192; e += 256) sB[e] = dtb[e];
    __syncthreads();
    int l = blockIdx.x * 256 + tid;
    int b = blockIdx.y;
    float r[6];
#pragma unroll
    for (int rr = 0; rr < 6; rr++) r[rr] = g_xdbl2[((long)b * 22 + rr) * LQ + l];
    float* dout = g_delta + (long)b * 192 * LQ + l;
    for (int d = 0; d < 192; d++) {
        float s = sB[d];
#pragma unroll
        for (int rr = 0; rr < 6; rr++) s += sW[d * 6 + rr] * r[rr];
        float sp = (s > 20.f) ? s : log1pf(expf(s));
        dout[(long)d * LQ] = sp;
    }
}

// ---------------- B/C assembly into [b][l][16] ----------------
__global__ void bc_kernel()
{
    int l = blockIdx.x * 256 + threadIdx.x;
    int b = blockIdx.y;
    float* o = g_BC + ((long)b * LQ + l) * 16;
#pragma unroll
    for (int n = 0; n < 8; n++) {
        float bs = g_xdbl2[((long)b * 22 + 6 + n) * LQ + l]  * g_yL[((long)b * 8 + n) * LQ + l] + 1e-6f;
        float cs = g_xdbl2[((long)b * 22 + 14 + n) * LQ + l] * g_ym[((long)b * 8 + n) * LQ + l] + 1e-6f;
        o[n] = bs;
        o[8 + n] = cs;
    }
}

// ---------------- selective scan: block per (b,d), two-pass chunked scan ----------------
__global__ void scan_kernel(const float* __restrict__ Ds)
{
    extern __shared__ float sm[];
    float* sDelta = sm;          // 4096
    float* sU = sm + 4096;       // 4096
    float* sScan = sm + 8192;    // 4096
    int bd = blockIdx.x;
    int b = bd / 192, d = bd % 192;
    int tid = threadIdx.x;
    const float* dp = g_delta + ((long)b * 192 + d) * LQ;
    const float* up = g_xc    + ((long)b * 192 + d) * LQ;
    for (int e = tid; e < LQ; e += 256) { sDelta[e] = dp[e]; sU[e] = up[e]; }
    float An[8];
#pragma unroll
    for (int n = 0; n < 8; n++) An[n] = g_A[d * 8 + n];
    __syncthreads();
    const float* bc = g_BC + (long)b * LQ * 16;

    float a[8], hh[8];
#pragma unroll
    for (int n = 0; n < 8; n++) { a[n] = 1.f; hh[n] = 0.f; }
    int base = tid * 16;
    for (int i = 0; i < 16; i++) {
        int l = base + i;
        float delta = sDelta[l];
        float du = delta * sU[l];
        const float4* bc4 = (const float4*)(bc + (long)l * 16);
        float4 b0 = bc4[0], b1 = bc4[1];
        float bl[8] = {b0.x,b0.y,b0.z,b0.w,b1.x,b1.y,b1.z,b1.w};
#pragma unroll
        for (int n = 0; n < 8; n++) {
            float p = __expf(delta * An[n]);
            hh[n] = p * hh[n] + du * bl[n];
            a[n] *= p;
        }
    }
#pragma unroll
    for (int n = 0; n < 8; n++) { sScan[n * 256 + tid] = a[n]; sScan[2048 + n * 256 + tid] = hh[n]; }
    __syncthreads();

    for (int off = 1; off < 256; off <<= 1) {
        float pa[8], pb[8];
        if (tid >= off) {
#pragma unroll
            for (int n = 0; n < 8; n++) {
                pa[n] = sScan[n * 256 + tid - off];
                pb[n] = sScan[2048 + n * 256 + tid - off];
            }
        }
        __syncthreads();
        if (tid >= off) {
#pragma unroll
            for (int n = 0; n < 8; n++) {
                float a2 = sScan[n * 256 + tid];
                float b2 = sScan[2048 + n * 256 + tid];
                sScan[n * 256 + tid] = pa[n] * a2;
                sScan[2048 + n * 256 + tid] = a2 * pb[n] + b2;
            }
        }
        __syncthreads();
    }
    float h0[8];
#pragma unroll
    for (int n = 0; n < 8; n++) h0[n] = (tid == 0) ? 0.f : sScan[2048 + n * 256 + tid - 1];
    __syncthreads();

    float Dd = Ds[d];
    for (int i = 0; i < 16; i++) {
        int l = base + i;
        float delta = sDelta[l];
        float u = sU[l];
        float du = delta * u;
        const float4* bc4 = (const float4*)(bc + (long)l * 16);
        float4 b0 = bc4[0], b1 = bc4[1], c0 = bc4[2], c1 = bc4[3];
        float bl[8] = {b0.x,b0.y,b0.z,b0.w,b1.x,b1.y,b1.z,b1.w};
        float cl[8] = {c0.x,c0.y,c0.z,c0.w,c1.x,c1.y,c1.z,c1.w};
        float y = Dd * u;
#pragma unroll
        for (int n = 0; n < 8; n++) {
            float p = __expf(delta * An[n]);
            h0[n] = p * h0[n] + du * bl[n];
            y += h0[n] * cl[n];
        }
        sScan[l] = y;
    }
    __syncthreads();
    float* yo = g_y + ((long)b * 192 + d) * LQ;
    for (int e = tid; e < LQ; e += 256) yo[e] = sScan[e];
}

// ---------------- LayerNorm over d + silu(z) gate ----------------
__global__ void ln_kernel(const float* __restrict__ gamma, const float* __restrict__ beta)
{
    __shared__ float sg[192], sb2[192];
    int tid = threadIdx.x;
    for (int e = tid; e < 192; e += 256) { sg[e] = gamma[e]; sb2[e] = beta[e]; }
    __syncthreads();
    int l = blockIdx.x * 256 + tid;
    int b = blockIdx.y;
    const float* yp = g_y + (long)b * 192 * LQ + l;
    float s = 0.f, ss = 0.f;
    for (int dd = 0; dd < 192; dd++) {
        float v = yp[(long)dd * LQ];
        s += v; ss += v * v;
    }
    float mu = s * (1.f / 192.f);
    float var = ss * (1.f / 192.f) - mu * mu;
    float rs = rsqrtf(var + 1e-5f);
    const float* zp = g_zsil + (long)b * 192 * LQ + l;
    float* op = g_yn + (long)b * 192 * LQ + l;
    for (int dd = 0; dd < 192; dd++) {
        float v = (yp[(long)dd * LQ] - mu) * rs * sg[dd] + sb2[dd];
        op[(long)dd * LQ] = v * zp[(long)dd * LQ];
    }
}

// ---------------- host launcher ----------------
extern "C" void kernel_launch(void* const* d_in, const int* in_sizes, int n_in,
                              void* d_out, int out_size)
{
    const float* x        = (const float*)d_in[0];
    const float* W_in     = (const float*)d_in[1];
    const float* W_dwc_i  = (const float*)d_in[2];
    const float* b_dwc_i  = (const float*)d_in[3];
    const float* W_dw3    = (const float*)d_in[4];
    const float* b_dw3    = (const float*)d_in[5];
    const float* W_dw5    = (const float*)d_in[6];
    const float* b_dw5    = (const float*)d_in[7];
    const float* W_dw7    = (const float*)d_in[8];
    const float* b_dw7    = (const float*)d_in[9];
    const float* W_dwc_f  = (const float*)d_in[10];
    const float* b_dwc_f  = (const float*)d_in[11];
    const float* W_conv2d = (const float*)d_in[12];
    const float* b_conv2d = (const float*)d_in[13];
    const float* W_haar   = (const float*)d_in[14];
    const float* x_proj_w = (const float*)d_in[15];
    const float* W_xconv  = (const float*)d_in[16];
    const float* b_xconv  = (const float*)d_in[17];
    const float* dt_w     = (const float*)d_in[18];
    const float* dt_b     = (const float*)d_in[19];
    const float* A_logs   = (const float*)d_in[20];
    const float* Ds       = (const float*)d_in[21];
    const float* ln_g     = (const float*)d_in[22];
    const float* ln_b     = (const float*)d_in[23];
    const float* W_out    = (const float*)d_in[24];
    float* out = (float*)d_out;

    float *p_xz, *p_t, *p_t2, *p_zf, *p_xc, *p_xdbl, *p_yn;
    float *p_WinT, *p_Wd1T, *p_WdfT, *p_WxpT, *p_WoutT;
    cudaGetSymbolAddress((void**)&p_xz, g_xz);
    cudaGetSymbolAddress((void**)&p_t, g_t);
    cudaGetSymbolAddress((void**)&p_t2, g_t2);
    cudaGetSymbolAddress((void**)&p_zf, g_zf);
    cudaGetSymbolAddress((void**)&p_xc, g_xc);
    cudaGetSymbolAddress((void**)&p_xdbl, g_xdbl);
    cudaGetSymbolAddress((void**)&p_yn, g_yn);
    cudaGetSymbolAddress((void**)&p_WinT, g_WinT);
    cudaGetSymbolAddress((void**)&p_Wd1T, g_Wd1T);
    cudaGetSymbolAddress((void**)&p_WdfT, g_WdfT);
    cudaGetSymbolAddress((void**)&p_WxpT, g_WxpT);
    cudaGetSymbolAddress((void**)&p_WoutT, g_WoutT);

    cudaFuncSetAttribute(haar_kernel, cudaFuncAttributeMaxDynamicSharedMemorySize, 73728);
    cudaFuncSetAttribute(scan_kernel, cudaFuncAttributeMaxDynamicSharedMemorySize, 49152);

    prep_kernel<<<288, 256>>>(W_in, W_dwc_i, W_dwc_f, x_proj_w, W_out, A_logs);

    // K1: input GEMM  x[b,96,L] -> xz[b,384,L]
    gemm128_kernel<<<dim3(32, 6, NB), 128>>>(x, 96L * LQ, p_WinT, nullptr,
                                             p_xz, 384L * LQ, 384, 96);
    // K2: z branch 1x1 init conv (K=192 -> 384)
    gemm128_kernel<<<dim3(32, 6, NB), 128>>>(p_xz + 192L * LQ, 384L * LQ, p_Wd1T, b_dwc_i,
                                             p_t, 384L * LQ, 384, 192);
    // K3: multi-scale depthwise + gelu
    gelu_copy_kernel<<<(int)((long)NB * 96 * LQ / 256), 256>>>();
    dwconv_gelu_kernel<3><<<dim3(96, NB), 256>>>(W_dw3, b_dw3, 96);
    dwconv_gelu_kernel<5><<<dim3(96, NB), 256>>>(W_dw5, b_dw5, 192);
    dwconv_gelu_kernel<7><<<dim3(96, NB), 256>>>(W_dw7, b_dw7, 288);
    // K4: z branch final 1x1 conv (K=384 -> 192)
    gemm128_kernel<<<dim3(32, 3, NB), 128>>>(p_t2, 384L * LQ, p_WdfT, b_dwc_f,
                                             p_zf, 192L * LQ, 192, 384);
    // K4b: transpose + silu gate
    ztrans_kernel<<<dim3(2, 2, NB * 192), dim3(32, 8)>>>();
    // K5: x branch depthwise 3x3 + silu
    dw3_silu_kernel<<<dim3(192, NB), 256>>>(W_conv2d, b_conv2d);
    // K6: haar -> yL, y_mean
    haar_kernel<<<dim3(32, NB), 256, 73728>>>(W_haar);
    // K7a: x_proj GEMM (K=192 -> 22)
    gemm_kernel<<<dim3(64, 1, NB), 128>>>(p_xc, 192L * LQ, p_WxpT, nullptr,
                                          p_xdbl, 22L * LQ, 22, 192);
    // K7b: depthwise conv1d k=7
    conv1d_kernel<<<dim3(16, NB * 22), 256>>>(W_xconv, b_xconv);
    // K7c: dt projection + softplus
    dtproj_kernel<<<dim3(16, NB), 256>>>(dt_w, dt_b);
    // K7d: Bs/Cs assembly
    bc_kernel<<<dim3(16, NB), 256>>>();
    // K8: selective scan
    scan_kernel<<<NB * 192, 256, 49152>>>(Ds);
    // K9a: layernorm + gate
    ln_kernel<<<dim3(16, NB), 256>>>(ln_g, ln_b);
    // K9b: output GEMM (K=192 -> 96) straight into d_out
    gemm128_kernel<<<dim3(32, 2, NB), 128>>>(p_yn, 192L * LQ, p_WoutT, nullptr,
                                             out, 96L * LQ, 96, 192);
    (void)in_sizes; (void)n_in; (void)out_size;
}

// round 5
// speedup vs baseline: 1.8624x; 1.2813x over previous
#include <cuda_runtime.h>
#include <cuda_bf16.h>
#include <stdint.h>
#include <math.h>

#define NB 8
#define LQ 4096

// ---------------- device scratch (zero-init BSS, no allocation) ----------------
__device__ float g_xz   [(long)NB*384*LQ];
__device__ float g_t    [(long)NB*384*LQ];
__device__ float g_t2   [(long)NB*384*LQ];
__device__ float g_zf   [(long)NB*192*LQ];
__device__ float g_zsil [(long)NB*192*LQ];
__device__ float g_xc   [(long)NB*192*LQ];
__device__ float g_yL   [(long)NB*8*LQ];
__device__ float g_ym   [(long)NB*8*LQ];
__device__ float g_xdbl [(long)NB*22*LQ];
__device__ float g_xdbl2[(long)NB*22*LQ];
__device__ float g_delta[(long)NB*192*LQ];
__device__ float g_BC   [(long)NB*LQ*16];
__device__ float g_y    [(long)NB*192*LQ];
__device__ float g_yn   [(long)NB*192*LQ];
__device__ float g_A    [192*8];

__device__ float g_WinT  [96*384];
__device__ float g_WxpT  [192*22];
__device__ float g_WoutT [192*96];

// ---------------- prep: transpose weights + materialize A ----------------
__global__ void prep_kernel(const float* __restrict__ Win, const float* __restrict__ Wxp,
                            const float* __restrict__ Wout, const float* __restrict__ Alogs)
{
    int t = blockIdx.x * 256 + threadIdx.x;
    if (t < 384*96)  { int n = t/96,  k = t%96;  g_WinT[k*384 + n] = Win[t]; }
    if (t < 22*192)  { int n = t/192, k = t%192; g_WxpT[k*22  + n] = Wxp[t]; }
    if (t < 96*192)  { int n = t/192, k = t%192; g_WoutT[k*96 + n] = Wout[t]; }
    if (t < 192*8)   g_A[t] = -expf(Alogs[t]);
}

// ---------------- tf32 tensor-core GEMM ----------------
// O[n][m] = bias[n] + sum_k Act[k][m] * W[n][k]
// W in ORIGINAL [N][K] layout (k contiguous). Act [K][4096] (m contiguous).
// Block tile: n=64, m=128, k-chunk=32. 256 threads = 8 warps (2 n x 4 m), warp tile 32x32.
__device__ __forceinline__ uint32_t f2tf32(float f)
{
    uint32_t o;
    asm("cvt.rna.tf32.f32 %0, %1;" : "=r"(o) : "f"(f));
    return o;
}

__device__ __forceinline__ void mma_tf32(float* d, const uint32_t* a, const uint32_t* b)
{
    asm volatile("mma.sync.aligned.m16n8k8.row.col.f32.tf32.tf32.f32 "
                 "{%0,%1,%2,%3}, {%4,%5,%6,%7}, {%8,%9}, {%0,%1,%2,%3};"
                 : "+f"(d[0]), "+f"(d[1]), "+f"(d[2]), "+f"(d[3])
                 : "r"(a[0]), "r"(a[1]), "r"(a[2]), "r"(a[3]),
                   "r"(b[0]), "r"(b[1]));
}

__global__ void __launch_bounds__(256)
gemm_tf32_kernel(const float* __restrict__ Act, long actStride,
                 const float* __restrict__ W, const float* __restrict__ bias,
                 float* __restrict__ O, long oStride, int N, int K)
{
    __shared__ uint32_t sW[64][36];     // [n][k], pad 36: conflict-free a-frag reads
    __shared__ uint32_t sAct[32][136];  // [k][m], pad 136: conflict-free b-frag reads
    const float* Ab = Act + (long)blockIdx.z * actStride;
    float* Ob = O + (long)blockIdx.z * oStride;
    int m0 = blockIdx.x * 128, n0 = blockIdx.y * 64;
    int tid = threadIdx.x, lane = tid & 31, wid = tid >> 5;
    int wn = (wid & 1) * 32;   // warp n offset in tile
    int wm = (wid >> 1) * 32;  // warp m offset in tile

    float d[2][4][4];
#pragma unroll
    for (int i = 0; i < 2; i++)
#pragma unroll
        for (int j = 0; j < 4; j++)
#pragma unroll
            for (int q = 0; q < 4; q++) d[i][j][q] = 0.f;

    for (int kc = 0; kc < K; kc += 32) {
        // load W tile [64 n][32 k]
#pragma unroll
        for (int i = 0; i < 2; i++) {
            int e = tid + i * 256;
            int row = e >> 3, c4 = (e & 7) * 4;
            float4 v = *(const float4*)(W + (long)(n0 + row) * K + kc + c4);
            sW[row][c4 + 0] = f2tf32(v.x);
            sW[row][c4 + 1] = f2tf32(v.y);
            sW[row][c4 + 2] = f2tf32(v.z);
            sW[row][c4 + 3] = f2tf32(v.w);
        }
        // load Act tile [32 k][128 m]
#pragma unroll
        for (int i = 0; i < 4; i++) {
            int e = tid + i * 256;
            int row = e >> 5, c4 = (e & 31) * 4;
            float4 v = *(const float4*)(Ab + (long)(kc + row) * LQ + m0 + c4);
            sAct[row][c4 + 0] = f2tf32(v.x);
            sAct[row][c4 + 1] = f2tf32(v.y);
            sAct[row][c4 + 2] = f2tf32(v.z);
            sAct[row][c4 + 3] = f2tf32(v.w);
        }
        __syncthreads();

#pragma unroll
        for (int ks = 0; ks < 4; ks++) {
            int kk = ks * 8;
            uint32_t afr[2][4], bfr[4][2];
            int r = wn + (lane >> 2);
            int c = kk + (lane & 3);
#pragma unroll
            for (int i = 0; i < 2; i++) {
                int rb = r + i * 16;
                afr[i][0] = sW[rb][c];
                afr[i][1] = sW[rb + 8][c];
                afr[i][2] = sW[rb][c + 4];
                afr[i][3] = sW[rb + 8][c + 4];
            }
            int mcol = wm + (lane >> 2);
            int krow = kk + (lane & 3);
#pragma unroll
            for (int j = 0; j < 4; j++) {
                bfr[j][0] = sAct[krow][mcol + j * 8];
                bfr[j][1] = sAct[krow + 4][mcol + j * 8];
            }
#pragma unroll
            for (int i = 0; i < 2; i++)
#pragma unroll
                for (int j = 0; j < 4; j++)
                    mma_tf32(d[i][j], afr[i], bfr[j]);
        }
        __syncthreads();
    }

    // epilogue: c0,c1 at (row, 2c),(row,2c+1); c2,c3 at row+8
#pragma unroll
    for (int i = 0; i < 2; i++) {
        int n = n0 + wn + i * 16 + (lane >> 2);
        float bb0 = bias ? bias[n] : 0.f;
        float bb1 = bias ? bias[n + 8] : 0.f;
#pragma unroll
        for (int j = 0; j < 4; j++) {
            int m = m0 + wm + j * 8 + 2 * (lane & 3);
            float* p0 = Ob + (long)n * LQ + m;
            float* p1 = Ob + (long)(n + 8) * LQ + m;
            p0[0] = d[i][j][0] + bb0;
            p0[1] = d[i][j][1] + bb0;
            p1[0] = d[i][j][2] + bb1;
            p1[1] = d[i][j][3] + bb1;
        }
    }
}

// ---------------- big-tile fp32 GEMM (kept for K1/K9b) ----------------
__global__ void __launch_bounds__(128, 4)
gemm128_kernel(const float* __restrict__ A, long aStride,
               const float* __restrict__ WT,
               const float* __restrict__ bias,
               float* __restrict__ O, long oStride,
               int N, int K)
{
    __shared__ float sA[2][16][128];
    __shared__ float sW[2][16][64];
    const float* Ab = A + (long)blockIdx.z * aStride;
    float* Ob = O + (long)blockIdx.z * oStride;
    int m0 = blockIdx.x * 128, n0 = blockIdx.y * 64;
    int tid = threadIdx.x;
    int tm = tid & 15, tn = tid >> 4;

    int arow = tid >> 5;
    int acol = (tid & 31) * 4;

    float acc[8][8];
#pragma unroll
    for (int j = 0; j < 8; j++)
#pragma unroll
        for (int i = 0; i < 8; i++) acc[j][i] = 0.f;

    {
#pragma unroll
        for (int r = 0; r < 4; r++) {
            int kk = arow + 4 * r;
            float4 v = *(const float4*)(Ab + (long)kk * LQ + m0 + acol);
            *(float4*)&sA[0][kk][acol] = v;
        }
#pragma unroll
        for (int r = 0; r < 8; r++) {
            int e = tid + r * 128;
            int kk = e >> 6, mm = e & 63;
            int n = n0 + mm;
            sW[0][kk][mm] = (n < N) ? WT[(long)kk * N + n] : 0.f;
        }
    }
    __syncthreads();

    int nTiles = K >> 4;
    for (int kt = 0; kt < nTiles; kt++) {
        int cur = kt & 1, nxt = cur ^ 1;
        float4 pA[4];
        float pW[8];
        bool hasNext = (kt + 1 < nTiles);
        if (hasNext) {
            int kb = (kt + 1) << 4;
#pragma unroll
            for (int r = 0; r < 4; r++) {
                int kk = arow + 4 * r;
                pA[r] = *(const float4*)(Ab + (long)(kb + kk) * LQ + m0 + acol);
            }
#pragma unroll
            for (int r = 0; r < 8; r++) {
                int e = tid + r * 128;
                int kk = e >> 6, mm = e & 63;
                int n = n0 + mm;
                pW[r] = (n < N) ? WT[(long)(kb + kk) * N + n] : 0.f;
            }
        }
#pragma unroll
        for (int kk = 0; kk < 16; kk++) {
            float4 a0 = *(const float4*)&sA[cur][kk][tm * 8];
            float4 a1 = *(const float4*)&sA[cur][kk][tm * 8 + 4];
            float4 b0 = *(const float4*)&sW[cur][kk][tn * 8];
            float4 b1 = *(const float4*)&sW[cur][kk][tn * 8 + 4];
            float av[8] = {a0.x,a0.y,a0.z,a0.w,a1.x,a1.y,a1.z,a1.w};
            float bv[8] = {b0.x,b0.y,b0.z,b0.w,b1.x,b1.y,b1.z,b1.w};
#pragma unroll
            for (int j = 0; j < 8; j++)
#pragma unroll
                for (int i = 0; i < 8; i++) acc[j][i] += av[i] * bv[j];
        }
        if (hasNext) {
#pragma unroll
            for (int r = 0; r < 4; r++) {
                int kk = arow + 4 * r;
                *(float4*)&sA[nxt][kk][acol] = pA[r];
            }
#pragma unroll
            for (int r = 0; r < 8; r++) {
                int e = tid + r * 128;
                int kk = e >> 6, mm = e & 63;
                sW[nxt][kk][mm] = pW[r];
            }
        }
        __syncthreads();
    }

#pragma unroll
    for (int j = 0; j < 8; j++) {
        int n = n0 + tn * 8 + j;
        if (n < N) {
            float bb = bias ? bias[n] : 0.f;
            float* orow = Ob + (long)n * LQ + m0 + tm * 8;
            float4 v0 = make_float4(acc[j][0]+bb, acc[j][1]+bb, acc[j][2]+bb, acc[j][3]+bb);
            float4 v1 = make_float4(acc[j][4]+bb, acc[j][5]+bb, acc[j][6]+bb, acc[j][7]+bb);
            *(float4*)orow = v0;
            *(float4*)(orow + 4) = v1;
        }
    }
}

// ---------------- small-N fp32 GEMM (N=22) ----------------
__global__ void gemm_kernel(const float* __restrict__ A, long aStride,
                            const float* __restrict__ WT,
                            const float* __restrict__ bias,
                            float* __restrict__ O, long oStride,
                            int N, int K)
{
    __shared__ float sA[16][64];
    __shared__ float sW[16][64];
    const float* Ab = A + (long)blockIdx.z * aStride;
    float* Ob = O + (long)blockIdx.z * oStride;
    int m0 = blockIdx.x * 64, n0 = blockIdx.y * 64;
    int tid = threadIdx.x;
    int tm = tid & 15, tn = tid >> 4;
    float acc[8][4];
#pragma unroll
    for (int j = 0; j < 8; j++)
#pragma unroll
        for (int i = 0; i < 4; i++) acc[j][i] = 0.f;

    for (int kt = 0; kt < K; kt += 16) {
#pragma unroll
        for (int r = 0; r < 8; r++) {
            int e = tid + r * 128;
            int kk = e >> 6, mm = e & 63;
            sA[kk][mm] = Ab[(long)(kt + kk) * LQ + m0 + mm];
            int n = n0 + mm;
            sW[kk][mm] = (n < N) ? WT[(long)(kt + kk) * N + n] : 0.f;
        }
        __syncthreads();
#pragma unroll
        for (int kk = 0; kk < 16; kk++) {
            float av[4], bv[8];
#pragma unroll
            for (int i = 0; i < 4; i++) av[i] = sA[kk][tm * 4 + i];
#pragma unroll
            for (int j = 0; j < 8; j++) bv[j] = sW[kk][tn * 8 + j];
#pragma unroll
            for (int j = 0; j < 8; j++)
#pragma unroll
                for (int i = 0; i < 4; i++) acc[j][i] += av[i] * bv[j];
        }
        __syncthreads();
    }
#pragma unroll
    for (int j = 0; j < 8; j++) {
        int n = n0 + tn * 8 + j;
        if (n < N) {
            float bb = bias ? bias[n] : 0.f;
            float* orow = Ob + (long)n * LQ + m0 + tm * 4;
#pragma unroll
            for (int i = 0; i < 4; i++) orow[i] = acc[j][i] + bb;
        }
    }
}

// ---------------- z branch: smem-tiled depthwise conv + exact GELU ----
__device__ __forceinline__ float gelu_exact(float v)
{
    return 0.5f * v * (1.f + erff(v * 0.70710678118654752f));
}

template<int KSZ>
__global__ void dwconv_gelu_kernel(const float* __restrict__ W, const float* __restrict__ bias,
                                   int coBase)
{
    constexpr int PAD = KSZ / 2;
    constexpr int SH = 64 + 2 * PAD;
    __shared__ float sm[SH * 72];
    int c = blockIdx.x;
    int b = blockIdx.y;
    int co = coBase + c;
    int tid = threadIdx.x;
    const float* src = g_t + ((long)b * 384 + co) * LQ;

    for (int e = tid; e < SH * 72; e += 256) sm[e] = 0.f;
    __syncthreads();
    for (int e = tid; e < LQ; e += 256) {
        int h = e >> 6, w = e & 63;
        sm[(h + PAD) * 72 + (w + PAD)] = src[e];
    }
    __syncthreads();

    float wreg[KSZ * KSZ];
#pragma unroll
    for (int i = 0; i < KSZ * KSZ; i++) wreg[i] = W[c * KSZ * KSZ + i];
    float bb = bias[c];

    float* dst = g_t2 + ((long)b * 384 + co) * LQ;
    for (int e = tid; e < LQ; e += 256) {
        int h = e >> 6, w = e & 63;
        float acc = bb;
#pragma unroll
        for (int ky = 0; ky < KSZ; ky++) {
            const float* row = sm + (h + ky) * 72 + w;
#pragma unroll
            for (int kx = 0; kx < KSZ; kx++)
                acc += row[kx] * wreg[ky * KSZ + kx];
        }
        dst[e] = gelu_exact(acc);
    }
}

__global__ void gelu_copy_kernel()
{
    long idx = (long)blockIdx.x * 256 + threadIdx.x;
    int b = (int)(idx / (96L * LQ));
    long rem = idx - (long)b * 96 * LQ;
    int c = (int)(rem / LQ);
    int l = (int)(rem - (long)c * LQ);
    long off = ((long)b * 384 + c) * LQ + l;
    g_t2[off] = gelu_exact(g_t[off]);
}

// ---------------- zf spatial transpose + silu ----------------
__global__ void ztrans_kernel()
{
    __shared__ float tile[32][33];
    long bd = blockIdx.z;
    int ti = blockIdx.y * 32, tj = blockIdx.x * 32;
    const float* src = g_zf + bd * LQ;
    float* dst = g_zsil + bd * LQ;
    int tx = threadIdx.x, ty = threadIdx.y;
#pragma unroll
    for (int r = 0; r < 32; r += 8)
        tile[ty + r][tx] = src[(ti + ty + r) * 64 + tj + tx];
    __syncthreads();
#pragma unroll
    for (int r = 0; r < 32; r += 8) {
        int a = ty + r;
        float v = tile[tx][a];
        dst[(tj + a) * 64 + ti + tx] = v / (1.f + __expf(-v));
    }
}

// ---------------- x branch: depthwise 3x3 + bias + silu ----------------
__global__ void dw3_silu_kernel(const float* __restrict__ W, const float* __restrict__ bias)
{
    __shared__ float sm[66 * 68];
    int c = blockIdx.x;
    int b = blockIdx.y;
    int tid = threadIdx.x;
    const float* src = g_xz + ((long)b * 384 + c) * LQ;
    for (int e = tid; e < 66 * 68; e += 256) sm[e] = 0.f;
    __syncthreads();
    for (int e = tid; e < LQ; e += 256) {
        int h = e >> 6, w = e & 63;
        sm[(h + 1) * 68 + (w + 1)] = src[e];
    }
    __syncthreads();
    float w0 = W[c*9+0], w1 = W[c*9+1], w2 = W[c*9+2];
    float w3 = W[c*9+3], w4 = W[c*9+4], w5 = W[c*9+5];
    float w6 = W[c*9+6], w7 = W[c*9+7], w8 = W[c*9+8];
    float bb = bias[c];
    float* dst = g_xc + ((long)b * 192 + c) * LQ;
    for (int e = tid; e < LQ; e += 256) {
        int h = e >> 6, w = e & 63;
        const float* r0 = sm + h * 68 + w;
        float acc = bb + r0[0]*w0 + r0[1]*w1 + r0[2]*w2
                       + r0[68]*w3 + r0[69]*w4 + r0[70]*w5
                       + r0[136]*w6 + r0[137]*w7 + r0[138]*w8;
        dst[e] = acc / (1.f + __expf(-acc));
    }
}

// ---------------- haar 1x1 conv + strided combine -> yL, y_mean ----------------
__global__ void haar_kernel(const float* __restrict__ Wh)
{
    extern __shared__ float smh[];
    float* sW = smh;
    float* s1 = smh + 32 * 192;
    float* s2 = s1 + 192 * 32;
    int i = blockIdx.x, b = blockIdx.y;
    int tid = threadIdx.x;
    for (int e = tid; e < 32 * 192; e += 256) sW[e] = Wh[e];
    const float* xcb = g_xc + (long)b * 192 * LQ;
    for (int e = tid; e < 192 * 32; e += 256) {
        int d = e >> 5, j = e & 31;
        const float* row0 = xcb + (long)d * LQ + (2 * i) * 64 + 2 * j;
        float xa = row0[0], xb = row0[1];
        float xc2 = row0[64], xd = row0[65];
        s1[d * 32 + j] = xa + xb + xc2 + xd;
        s2[d * 32 + j] = 3.f * xa - xb - xc2 - xd;
    }
    __syncthreads();
    for (int e = tid; e < 2048; e += 256) {
        int which = e >> 10;
        int ch = (e >> 5) & 31;
        int j = e & 31;
        const float* sv = (which ? s2 : s1) + j;
        const float* wr = sW + ch * 192;
        float acc = 0.f;
#pragma unroll 4
        for (int d = 0; d < 192; d++) acc += wr[d] * sv[d * 32];
        acc *= which ? (1.f / 6.f) : 0.5f;
        int n = ch >> 2;
        int lpos = (ch & 3) * 1024 + i * 32 + j;
        float* dst = which ? g_ym : g_yL;
        dst[((long)b * 8 + n) * LQ + lpos] = acc;
    }
}

// ---------------- depthwise conv1d k=7 pad=3 ----------------
__global__ void conv1d_kernel(const float* __restrict__ Wx, const float* __restrict__ bx)
{
    int l = blockIdx.x * 256 + threadIdx.x;
    int bc = blockIdx.y;
    int b = bc / 22, c = bc % 22;
    const float* src = g_xdbl + ((long)b * 22 + c) * LQ;
    float acc = bx[c];
#pragma unroll
    for (int k = 0; k < 7; k++) {
        int ll = l + k - 3;
        if ((unsigned)ll < (unsigned)LQ) acc += src[ll] * Wx[c * 7 + k];
    }
    g_xdbl2[((long)b * 22 + c) * LQ + l] = acc;
}

// ---------------- dt projection + softplus ----------------
__global__ void dtproj_kernel(const float* __restrict__ Wdt, const float* __restrict__ dtb)
{
    __shared__ float sW[192 * 6];
    __shared__ float sB[192];
    int tid = threadIdx.x;
    for (int e = tid; e < 1152; e += 256) sW[e] = Wdt[e];
    for (int e = tid; e < 192; e += 256) sB[e] = dtb[e];
    __syncthreads();
    int l = blockIdx.x * 256 + tid;
    int b = blockIdx.y;
    float r[6];
#pragma unroll
    for (int rr = 0; rr < 6; rr++) r[rr] = g_xdbl2[((long)b * 22 + rr) * LQ + l];
    float* dout = g_delta + (long)b * 192 * LQ + l;
    for (int d = 0; d < 192; d++) {
        float s = sB[d];
#pragma unroll
        for (int rr = 0; rr < 6; rr++) s += sW[d * 6 + rr] * r[rr];
        float sp = (s > 20.f) ? s : log1pf(expf(s));
        dout[(long)d * LQ] = sp;
    }
}

// ---------------- B/C assembly ----------------
__global__ void bc_kernel()
{
    int l = blockIdx.x * 256 + threadIdx.x;
    int b = blockIdx.y;
    float* o = g_BC + ((long)b * LQ + l) * 16;
#pragma unroll
    for (int n = 0; n < 8; n++) {
        float bs = g_xdbl2[((long)b * 22 + 6 + n) * LQ + l]  * g_yL[((long)b * 8 + n) * LQ + l] + 1e-6f;
        float cs = g_xdbl2[((long)b * 22 + 14 + n) * LQ + l] * g_ym[((long)b * 8 + n) * LQ + l] + 1e-6f;
        o[n] = bs;
        o[8 + n] = cs;
    }
}

// ---------------- selective scan ----------------
__global__ void scan_kernel(const float* __restrict__ Ds)
{
    extern __shared__ float sm[];
    float* sDelta = sm;
    float* sU = sm + 4096;
    float* sScan = sm + 8192;
    int bd = blockIdx.x;
    int b = bd / 192, d = bd % 192;
    int tid = threadIdx.x;
    const float* dp = g_delta + ((long)b * 192 + d) * LQ;
    const float* up = g_xc    + ((long)b * 192 + d) * LQ;
    for (int e = tid; e < LQ; e += 256) { sDelta[e] = dp[e]; sU[e] = up[e]; }
    float An[8];
#pragma unroll
    for (int n = 0; n < 8; n++) An[n] = g_A[d * 8 + n];
    __syncthreads();
    const float* bc = g_BC + (long)b * LQ * 16;

    float a[8], hh[8];
#pragma unroll
    for (int n = 0; n < 8; n++) { a[n] = 1.f; hh[n] = 0.f; }
    int base = tid * 16;
    for (int i = 0; i < 16; i++) {
        int l = base + i;
        float delta = sDelta[l];
        float du = delta * sU[l];
        const float4* bc4 = (const float4*)(bc + (long)l * 16);
        float4 b0 = bc4[0], b1 = bc4[1];
        float bl[8] = {b0.x,b0.y,b0.z,b0.w,b1.x,b1.y,b1.z,b1.w};
#pragma unroll
        for (int n = 0; n < 8; n++) {
            float p = __expf(delta * An[n]);
            hh[n] = p * hh[n] + du * bl[n];
            a[n] *= p;
        }
    }
#pragma unroll
    for (int n = 0; n < 8; n++) { sScan[n * 256 + tid] = a[n]; sScan[2048 + n * 256 + tid] = hh[n]; }
    __syncthreads();

    for (int off = 1; off < 256; off <<= 1) {
        float pa[8], pb[8];
        if (tid >= off) {
#pragma unroll
            for (int n = 0; n < 8; n++) {
                pa[n] = sScan[n * 256 + tid - off];
                pb[n] = sScan[2048 + n * 256 + tid - off];
            }
        }
        __syncthreads();
        if (tid >= off) {
#pragma unroll
            for (int n = 0; n < 8; n++) {
                float a2 = sScan[n * 256 + tid];
                float b2 = sScan[2048 + n * 256 + tid];
                sScan[n * 256 + tid] = pa[n] * a2;
                sScan[2048 + n * 256 + tid] = a2 * pb[n] + b2;
            }
        }
        __syncthreads();
    }
    float h0[8];
#pragma unroll
    for (int n = 0; n < 8; n++) h0[n] = (tid == 0) ? 0.f : sScan[2048 + n * 256 + tid - 1];
    __syncthreads();

    float Dd = Ds[d];
    for (int i = 0; i < 16; i++) {
        int l = base + i;
        float delta = sDelta[l];
        float u = sU[l];
        float du = delta * u;
        const float4* bc4 = (const float4*)(bc + (long)l * 16);
        float4 b0 = bc4[0], b1 = bc4[1], c0 = bc4[2], c1 = bc4[3];
        float bl[8] = {b0.x,b0.y,b0.z,b0.w,b1.x,b1.y,b1.z,b1.w};
        float cl[8] = {c0.x,c0.y,c0.z,c0.w,c1.x,c1.y,c1.z,c1.w};
        float y = Dd * u;
#pragma unroll
        for (int n = 0; n < 8; n++) {
            float p = __expf(delta * An[n]);
            h0[n] = p * h0[n] + du * bl[n];
            y += h0[n] * cl[n];
        }
        sScan[l] = y;
    }
    __syncthreads();
    float* yo = g_y + ((long)b * 192 + d) * LQ;
    for (int e = tid; e < LQ; e += 256) yo[e] = sScan[e];
}

// ---------------- LayerNorm + silu(z) gate ----------------
__global__ void ln_kernel(const float* __restrict__ gamma, const float* __restrict__ beta)
{
    __shared__ float sg[192], sb2[192];
    int tid = threadIdx.x;
    for (int e = tid; e < 192; e += 256) { sg[e] = gamma[e]; sb2[e] = beta[e]; }
    __syncthreads();
    int l = blockIdx.x * 256 + tid;
    int b = blockIdx.y;
    const float* yp = g_y + (long)b * 192 * LQ + l;
    float s = 0.f, ss = 0.f;
    for (int dd = 0; dd < 192; dd++) {
        float v = yp[(long)dd * LQ];
        s += v; ss += v * v;
    }
    float mu = s * (1.f / 192.f);
    float var = ss * (1.f / 192.f) - mu * mu;
    float rs = rsqrtf(var + 1e-5f);
    const float* zp = g_zsil + (long)b * 192 * LQ + l;
    float* op = g_yn + (long)b * 192 * LQ + l;
    for (int dd = 0; dd < 192; dd++) {
        float v = (yp[(long)dd * LQ] - mu) * rs * sg[dd] + sb2[dd];
        op[(long)dd * LQ] = v * zp[(long)dd * LQ];
    }
}

// ---------------- host launcher ----------------
extern "C" void kernel_launch(void* const* d_in, const int* in_sizes, int n_in,
                              void* d_out, int out_size)
{
    const float* x        = (const float*)d_in[0];
    const float* W_in     = (const float*)d_in[1];
    const float* W_dwc_i  = (const float*)d_in[2];
    const float* b_dwc_i  = (const float*)d_in[3];
    const float* W_dw3    = (const float*)d_in[4];
    const float* b_dw3    = (const float*)d_in[5];
    const float* W_dw5    = (const float*)d_in[6];
    const float* b_dw5    = (const float*)d_in[7];
    const float* W_dw7    = (const float*)d_in[8];
    const float* b_dw7    = (const float*)d_in[9];
    const float* W_dwc_f  = (const float*)d_in[10];
    const float* b_dwc_f  = (const float*)d_in[11];
    const float* W_conv2d = (const float*)d_in[12];
    const float* b_conv2d = (const float*)d_in[13];
    const float* W_haar   = (const float*)d_in[14];
    const float* x_proj_w = (const float*)d_in[15];
    const float* W_xconv  = (const float*)d_in[16];
    const float* b_xconv  = (const float*)d_in[17];
    const float* dt_w     = (const float*)d_in[18];
    const float* dt_b     = (const float*)d_in[19];
    const float* A_logs   = (const float*)d_in[20];
    const float* Ds       = (const float*)d_in[21];
    const float* ln_g     = (const float*)d_in[22];
    const float* ln_b     = (const float*)d_in[23];
    const float* W_out    = (const float*)d_in[24];
    float* out = (float*)d_out;

    float *p_xz, *p_t, *p_t2, *p_zf, *p_xc, *p_xdbl, *p_yn;
    float *p_WinT, *p_WxpT, *p_WoutT;
    cudaGetSymbolAddress((void**)&p_xz, g_xz);
    cudaGetSymbolAddress((void**)&p_t, g_t);
    cudaGetSymbolAddress((void**)&p_t2, g_t2);
    cudaGetSymbolAddress((void**)&p_zf, g_zf);
    cudaGetSymbolAddress((void**)&p_xc, g_xc);
    cudaGetSymbolAddress((void**)&p_xdbl, g_xdbl);
    cudaGetSymbolAddress((void**)&p_yn, g_yn);
    cudaGetSymbolAddress((void**)&p_WinT, g_WinT);
    cudaGetSymbolAddress((void**)&p_WxpT, g_WxpT);
    cudaGetSymbolAddress((void**)&p_WoutT, g_WoutT);

    cudaFuncSetAttribute(haar_kernel, cudaFuncAttributeMaxDynamicSharedMemorySize, 73728);
    cudaFuncSetAttribute(scan_kernel, cudaFuncAttributeMaxDynamicSharedMemorySize, 49152);

    prep_kernel<<<288, 256>>>(W_in, x_proj_w, W_out, A_logs);

    // K1: input GEMM x[b,96,L] -> xz[b,384,L] (fp32)
    gemm128_kernel<<<dim3(32, 6, NB), 128>>>(x, 96L * LQ, p_WinT, nullptr,
                                             p_xz, 384L * LQ, 384, 96);
    // K2: z branch 1x1 init conv (K=192 -> 384), tf32 tensor cores
    gemm_tf32_kernel<<<dim3(32, 6, NB), 256>>>(p_xz + 192L * LQ, 384L * LQ, W_dwc_i, b_dwc_i,
                                               p_t, 384L * LQ, 384, 192);
    // K3: multi-scale depthwise + gelu
    gelu_copy_kernel<<<(int)((long)NB * 96 * LQ / 256), 256>>>();
    dwconv_gelu_kernel<3><<<dim3(96, NB), 256>>>(W_dw3, b_dw3, 96);
    dwconv_gelu_kernel<5><<<dim3(96, NB), 256>>>(W_dw5, b_dw5, 192);
    dwconv_gelu_kernel<7><<<dim3(96, NB), 256>>>(W_dw7, b_dw7, 288);
    // K4: z branch final 1x1 conv (K=384 -> 192), tf32 tensor cores
    gemm_tf32_kernel<<<dim3(32, 3, NB), 256>>>(p_t2, 384L * LQ, W_dwc_f, b_dwc_f,
                                               p_zf, 192L * LQ, 192, 384);
    // K4b: transpose + silu gate
    ztrans_kernel<<<dim3(2, 2, NB * 192), dim3(32, 8)>>>();
    // K5: x branch depthwise 3x3 + silu
    dw3_silu_kernel<<<dim3(192, NB), 256>>>(W_conv2d, b_conv2d);
    // K6: haar -> yL, y_mean
    haar_kernel<<<dim3(32, NB), 256, 73728>>>(W_haar);
    // K7a: x_proj GEMM (K=192 -> 22)
    gemm_kernel<<<dim3(64, 1, NB), 128>>>(p_xc, 192L * LQ, p_WxpT, nullptr,
                                          p_xdbl, 22L * LQ, 22, 192);
    // K7b: depthwise conv1d k=7
    conv1d_kernel<<<dim3(16, NB * 22), 256>>>(W_xconv, b_xconv);
    // K7c: dt projection + softplus
    dtproj_kernel<<<dim3(16, NB), 256>>>(dt_w, dt_b);
    // K7d: Bs/Cs assembly
    bc_kernel<<<dim3(16, NB), 256>>>();
    // K8: selective scan
    scan_kernel<<<NB * 192, 256, 49152>>>(Ds);
    // K9a: layernorm + gate
    ln_kernel<<<dim3(16, NB), 256>>>(ln_g, ln_b);
    // K9b: output GEMM (K=192 -> 96) into d_out (fp32)
    gemm128_kernel<<<dim3(32, 2, NB), 128>>>(p_yn, 192L * LQ, p_WoutT, nullptr,
                                             out, 96L * LQ, 96, 192);
    (void)in_sizes; (void)n_in; (void)out_size;
}

// round 6
// speedup vs baseline: 1.8796x; 1.0093x over previous
#include <cuda_runtime.h>
#include <cuda_bf16.h>
#include <stdint.h>
#include <math.h>

#define NB 8
#define LQ 4096

// ---------------- device scratch (zero-init BSS, no allocation) ----------------
__device__ float g_xz   [(long)NB*384*LQ];
__device__ float g_t    [(long)NB*384*LQ];
__device__ float g_t2   [(long)NB*384*LQ];
__device__ float g_zf   [(long)NB*192*LQ];
__device__ float g_zsil [(long)NB*192*LQ];
__device__ float g_xc   [(long)NB*192*LQ];
__device__ float g_yL   [(long)NB*8*LQ];
__device__ float g_ym   [(long)NB*8*LQ];
__device__ float g_xdbl [(long)NB*22*LQ];
__device__ float g_xdbl2[(long)NB*22*LQ];
__device__ float g_delta[(long)NB*192*LQ];
__device__ float g_BC   [(long)NB*LQ*16];
__device__ float g_y    [(long)NB*192*LQ];
__device__ float g_yn   [(long)NB*192*LQ];
__device__ float g_A    [192*8];

// ---------------- prep: materialize A ----------------
__global__ void prep_kernel(const float* __restrict__ Alogs)
{
    int t = blockIdx.x * 256 + threadIdx.x;
    if (t < 192*8) g_A[t] = -expf(Alogs[t]);
}

// ---------------- tf32 tensor-core GEMM (optionally split/error-compensated) -----------
// O[n][m] = bias[n] + sum_k Act[k][m] * W[n][k]
// W in ORIGINAL [N][K] layout (k contiguous). Act [K][4096] (m contiguous).
// Block tile: n=64, m=128, k-chunk=32. 256 threads = 8 warps (2 n x 4 m), warp tile 32x32.
// SPLIT=true: 3xTF32 (big*big + big*small + small*big) => ~fp32 accuracy.
__device__ __forceinline__ uint32_t f2tf32(float f)
{
    uint32_t o;
    asm("cvt.rna.tf32.f32 %0, %1;" : "=r"(o) : "f"(f));
    return o;
}

__device__ __forceinline__ void mma_tf32(float* d, const uint32_t* a, const uint32_t* b)
{
    asm volatile("mma.sync.aligned.m16n8k8.row.col.f32.tf32.tf32.f32 "
                 "{%0,%1,%2,%3}, {%4,%5,%6,%7}, {%8,%9}, {%0,%1,%2,%3};"
                 : "+f"(d[0]), "+f"(d[1]), "+f"(d[2]), "+f"(d[3])
                 : "r"(a[0]), "r"(a[1]), "r"(a[2]), "r"(a[3]),
                   "r"(b[0]), "r"(b[1]));
}

template<bool SPLIT>
__global__ void __launch_bounds__(256)
gemm_tf32_kernel(const float* __restrict__ Act, long actStride,
                 const float* __restrict__ W, const float* __restrict__ bias,
                 float* __restrict__ O, long oStride, int N, int K)
{
    extern __shared__ uint32_t dsm[];
    // layout: sWb [64][36], (sWs [64][36]), sAb [32][136], (sAs [32][136])
    uint32_t* sWb = dsm;
    uint32_t* sWs = SPLIT ? (dsm + 64*36) : dsm;
    uint32_t* sAb = dsm + (SPLIT ? 2 : 1) * 64*36;
    uint32_t* sAs = SPLIT ? (sAb + 32*136) : sAb;

    const float* Ab = Act + (long)blockIdx.z * actStride;
    float* Ob = O + (long)blockIdx.z * oStride;
    int m0 = blockIdx.x * 128, n0 = blockIdx.y * 64;
    int tid = threadIdx.x, lane = tid & 31, wid = tid >> 5;
    int wn = (wid & 1) * 32;   // warp n offset in tile
    int wm = (wid >> 1) * 32;  // warp m offset in tile

    float d[2][4][4];
#pragma unroll
    for (int i = 0; i < 2; i++)
#pragma unroll
        for (int j = 0; j < 4; j++)
#pragma unroll
            for (int q = 0; q < 4; q++) d[i][j][q] = 0.f;

    for (int kc = 0; kc < K; kc += 32) {
        // load W tile [64 n][32 k]
#pragma unroll
        for (int i = 0; i < 2; i++) {
            int e = tid + i * 256;
            int row = e >> 3, c4 = (e & 7) * 4;
            int n = n0 + row;
            float4 v = make_float4(0.f, 0.f, 0.f, 0.f);
            if (n < N) v = *(const float4*)(W + (long)n * K + kc + c4);
            float vv[4] = {v.x, v.y, v.z, v.w};
#pragma unroll
            for (int t = 0; t < 4; t++) {
                uint32_t bg = f2tf32(vv[t]);
                sWb[row * 36 + c4 + t] = bg;
                if constexpr (SPLIT)
                    sWs[row * 36 + c4 + t] = f2tf32(vv[t] - __uint_as_float(bg));
            }
        }
        // load Act tile [32 k][128 m]
#pragma unroll
        for (int i = 0; i < 4; i++) {
            int e = tid + i * 256;
            int row = e >> 5, c4 = (e & 31) * 4;
            float4 v = *(const float4*)(Ab + (long)(kc + row) * LQ + m0 + c4);
            float vv[4] = {v.x, v.y, v.z, v.w};
#pragma unroll
            for (int t = 0; t < 4; t++) {
                uint32_t bg = f2tf32(vv[t]);
                sAb[row * 136 + c4 + t] = bg;
                if constexpr (SPLIT)
                    sAs[row * 136 + c4 + t] = f2tf32(vv[t] - __uint_as_float(bg));
            }
        }
        __syncthreads();

#pragma unroll
        for (int ks = 0; ks < 4; ks++) {
            int kk = ks * 8;
            uint32_t afrB[2][4], bfrB[4][2];
            uint32_t afrS[2][4], bfrS[4][2];
            int r = wn + (lane >> 2);
            int c = kk + (lane & 3);
#pragma unroll
            for (int i = 0; i < 2; i++) {
                int rb = r + i * 16;
                afrB[i][0] = sWb[rb * 36 + c];
                afrB[i][1] = sWb[(rb + 8) * 36 + c];
                afrB[i][2] = sWb[rb * 36 + c + 4];
                afrB[i][3] = sWb[(rb + 8) * 36 + c + 4];
                if constexpr (SPLIT) {
                    afrS[i][0] = sWs[rb * 36 + c];
                    afrS[i][1] = sWs[(rb + 8) * 36 + c];
                    afrS[i][2] = sWs[rb * 36 + c + 4];
                    afrS[i][3] = sWs[(rb + 8) * 36 + c + 4];
                }
            }
            int mcol = wm + (lane >> 2);
            int krow = kk + (lane & 3);
#pragma unroll
            for (int j = 0; j < 4; j++) {
                bfrB[j][0] = sAb[krow * 136 + mcol + j * 8];
                bfrB[j][1] = sAb[(krow + 4) * 136 + mcol + j * 8];
                if constexpr (SPLIT) {
                    bfrS[j][0] = sAs[krow * 136 + mcol + j * 8];
                    bfrS[j][1] = sAs[(krow + 4) * 136 + mcol + j * 8];
                }
            }
#pragma unroll
            for (int i = 0; i < 2; i++)
#pragma unroll
                for (int j = 0; j < 4; j++) {
                    if constexpr (SPLIT) {
                        mma_tf32(d[i][j], afrB[i], bfrS[j]);
                        mma_tf32(d[i][j], afrS[i], bfrB[j]);
                    }
                    mma_tf32(d[i][j], afrB[i], bfrB[j]);
                }
        }
        __syncthreads();
    }

    // epilogue: c0,c1 at (row, 2c),(row,2c+1); c2,c3 at row+8
#pragma unroll
    for (int i = 0; i < 2; i++) {
        int n = n0 + wn + i * 16 + (lane >> 2);
        float bb0 = (bias && n < N) ? bias[n] : 0.f;
        float bb1 = (bias && n + 8 < N) ? bias[n + 8] : 0.f;
#pragma unroll
        for (int j = 0; j < 4; j++) {
            int m = m0 + wm + j * 8 + 2 * (lane & 3);
            if (n < N) {
                float* p0 = Ob + (long)n * LQ + m;
                p0[0] = d[i][j][0] + bb0;
                p0[1] = d[i][j][1] + bb0;
            }
            if (n + 8 < N) {
                float* p1 = Ob + (long)(n + 8) * LQ + m;
                p1[0] = d[i][j][2] + bb1;
                p1[1] = d[i][j][3] + bb1;
            }
        }
    }
}

// ---------------- z branch: smem-tiled depthwise conv + exact GELU ----
__device__ __forceinline__ float gelu_exact(float v)
{
    return 0.5f * v * (1.f + erff(v * 0.70710678118654752f));
}

template<int KSZ>
__global__ void dwconv_gelu_kernel(const float* __restrict__ W, const float* __restrict__ bias,
                                   int coBase)
{
    constexpr int PAD = KSZ / 2;
    constexpr int SH = 64 + 2 * PAD;
    __shared__ float sm[SH * 72];
    int c = blockIdx.x;
    int b = blockIdx.y;
    int co = coBase + c;
    int tid = threadIdx.x;
    const float* src = g_t + ((long)b * 384 + co) * LQ;

    for (int e = tid; e < SH * 72; e += 256) sm[e] = 0.f;
    __syncthreads();
    for (int e = tid; e < LQ; e += 256) {
        int h = e >> 6, w = e & 63;
        sm[(h + PAD) * 72 + (w + PAD)] = src[e];
    }
    __syncthreads();

    float wreg[KSZ * KSZ];
#pragma unroll
    for (int i = 0; i < KSZ * KSZ; i++) wreg[i] = W[c * KSZ * KSZ + i];
    float bb = bias[c];

    float* dst = g_t2 + ((long)b * 384 + co) * LQ;
    for (int e = tid; e < LQ; e += 256) {
        int h = e >> 6, w = e & 63;
        float acc = bb;
#pragma unroll
        for (int ky = 0; ky < KSZ; ky++) {
            const float* row = sm + (h + ky) * 72 + w;
#pragma unroll
            for (int kx = 0; kx < KSZ; kx++)
                acc += row[kx] * wreg[ky * KSZ + kx];
        }
        dst[e] = gelu_exact(acc);
    }
}

__global__ void gelu_copy_kernel()
{
    long idx = (long)blockIdx.x * 256 + threadIdx.x;
    int b = (int)(idx / (96L * LQ));
    long rem = idx - (long)b * 96 * LQ;
    int c = (int)(rem / LQ);
    int l = (int)(rem - (long)c * LQ);
    long off = ((long)b * 384 + c) * LQ + l;
    g_t2[off] = gelu_exact(g_t[off]);
}

// ---------------- zf spatial transpose + silu ----------------
__global__ void ztrans_kernel()
{
    __shared__ float tile[32][33];
    long bd = blockIdx.z;
    int ti = blockIdx.y * 32, tj = blockIdx.x * 32;
    const float* src = g_zf + bd * LQ;
    float* dst = g_zsil + bd * LQ;
    int tx = threadIdx.x, ty = threadIdx.y;
#pragma unroll
    for (int r = 0; r < 32; r += 8)
        tile[ty + r][tx] = src[(ti + ty + r) * 64 + tj + tx];
    __syncthreads();
#pragma unroll
    for (int r = 0; r < 32; r += 8) {
        int a = ty + r;
        float v = tile[tx][a];
        dst[(tj + a) * 64 + ti + tx] = v / (1.f + __expf(-v));
    }
}

// ---------------- x branch: depthwise 3x3 + bias + silu ----------------
__global__ void dw3_silu_kernel(const float* __restrict__ W, const float* __restrict__ bias)
{
    __shared__ float sm[66 * 68];
    int c = blockIdx.x;
    int b = blockIdx.y;
    int tid = threadIdx.x;
    const float* src = g_xz + ((long)b * 384 + c) * LQ;
    for (int e = tid; e < 66 * 68; e += 256) sm[e] = 0.f;
    __syncthreads();
    for (int e = tid; e < LQ; e += 256) {
        int h = e >> 6, w = e & 63;
        sm[(h + 1) * 68 + (w + 1)] = src[e];
    }
    __syncthreads();
    float w0 = W[c*9+0], w1 = W[c*9+1], w2 = W[c*9+2];
    float w3 = W[c*9+3], w4 = W[c*9+4], w5 = W[c*9+5];
    float w6 = W[c*9+6], w7 = W[c*9+7], w8 = W[c*9+8];
    float bb = bias[c];
    float* dst = g_xc + ((long)b * 192 + c) * LQ;
    for (int e = tid; e < LQ; e += 256) {
        int h = e >> 6, w = e & 63;
        const float* r0 = sm + h * 68 + w;
        float acc = bb + r0[0]*w0 + r0[1]*w1 + r0[2]*w2
                       + r0[68]*w3 + r0[69]*w4 + r0[70]*w5
                       + r0[136]*w6 + r0[137]*w7 + r0[138]*w8;
        dst[e] = acc / (1.f + __expf(-acc));
    }
}

// ---------------- haar 1x1 conv + strided combine -> yL, y_mean ----------------
__global__ void haar_kernel(const float* __restrict__ Wh)
{
    extern __shared__ float smh[];
    float* sW = smh;
    float* s1 = smh + 32 * 192;
    float* s2 = s1 + 192 * 32;
    int i = blockIdx.x, b = blockIdx.y;
    int tid = threadIdx.x;
    for (int e = tid; e < 32 * 192; e += 256) sW[e] = Wh[e];
    const float* xcb = g_xc + (long)b * 192 * LQ;
    for (int e = tid; e < 192 * 32; e += 256) {
        int d = e >> 5, j = e & 31;
        const float* row0 = xcb + (long)d * LQ + (2 * i) * 64 + 2 * j;
        float xa = row0[0], xb = row0[1];
        float xc2 = row0[64], xd = row0[65];
        s1[d * 32 + j] = xa + xb + xc2 + xd;
        s2[d * 32 + j] = 3.f * xa - xb - xc2 - xd;
    }
    __syncthreads();
    for (int e = tid; e < 2048; e += 256) {
        int which = e >> 10;
        int ch = (e >> 5) & 31;
        int j = e & 31;
        const float* sv = (which ? s2 : s1) + j;
        const float* wr = sW + ch * 192;
        float acc = 0.f;
#pragma unroll 4
        for (int d = 0; d < 192; d++) acc += wr[d] * sv[d * 32];
        acc *= which ? (1.f / 6.f) : 0.5f;
        int n = ch >> 2;
        int lpos = (ch & 3) * 1024 + i * 32 + j;
        float* dst = which ? g_ym : g_yL;
        dst[((long)b * 8 + n) * LQ + lpos] = acc;
    }
}

// ---------------- depthwise conv1d k=7 pad=3 ----------------
__global__ void conv1d_kernel(const float* __restrict__ Wx, const float* __restrict__ bx)
{
    int l = blockIdx.x * 256 + threadIdx.x;
    int bc = blockIdx.y;
    int b = bc / 22, c = bc % 22;
    const float* src = g_xdbl + ((long)b * 22 + c) * LQ;
    float acc = bx[c];
#pragma unroll
    for (int k = 0; k < 7; k++) {
        int ll = l + k - 3;
        if ((unsigned)ll < (unsigned)LQ) acc += src[ll] * Wx[c * 7 + k];
    }
    g_xdbl2[((long)b * 22 + c) * LQ + l] = acc;
}

// ---------------- dt projection + softplus ----------------
__global__ void dtproj_kernel(const float* __restrict__ Wdt, const float* __restrict__ dtb)
{
    __shared__ float sW[192 * 6];
    __shared__ float sB[192];
    int tid = threadIdx.x;
    for (int e = tid; e < 1152; e += 256) sW[e] = Wdt[e];
    for (int e = tid; e < 192; e += 256) sB[e] = dtb[e];
    __syncthreads();
    int l = blockIdx.x * 256 + tid;
    int b = blockIdx.y;
    float r[6];
#pragma unroll
    for (int rr = 0; rr < 6; rr++) r[rr] = g_xdbl2[((long)b * 22 + rr) * LQ + l];
    float* dout = g_delta + (long)b * 192 * LQ + l;
    for (int d = 0; d < 192; d++) {
        float s = sB[d];
#pragma unroll
        for (int rr = 0; rr < 6; rr++) s += sW[d * 6 + rr] * r[rr];
        float sp = (s > 20.f) ? s : log1pf(expf(s));
        dout[(long)d * LQ] = sp;
    }
}

// ---------------- B/C assembly ----------------
__global__ void bc_kernel()
{
    int l = blockIdx.x * 256 + threadIdx.x;
    int b = blockIdx.y;
    float* o = g_BC + ((long)b * LQ + l) * 16;
#pragma unroll
    for (int n = 0; n < 8; n++) {
        float bs = g_xdbl2[((long)b * 22 + 6 + n) * LQ + l]  * g_yL[((long)b * 8 + n) * LQ + l] + 1e-6f;
        float cs = g_xdbl2[((long)b * 22 + 14 + n) * LQ + l] * g_ym[((long)b * 8 + n) * LQ + l] + 1e-6f;
        o[n] = bs;
        o[8 + n] = cs;
    }
}

// ---------------- selective scan ----------------
__global__ void scan_kernel(const float* __restrict__ Ds)
{
    extern __shared__ float sm[];
    float* sDelta = sm;
    float* sU = sm + 4096;
    float* sScan = sm + 8192;
    int bd = blockIdx.x;
    int b = bd / 192, d = bd % 192;
    int tid = threadIdx.x;
    const float* dp = g_delta + ((long)b * 192 + d) * LQ;
    const float* up = g_xc    + ((long)b * 192 + d) * LQ;
    for (int e = tid; e < LQ; e += 256) { sDelta[e] = dp[e]; sU[e] = up[e]; }
    float An[8];
#pragma unroll
    for (int n = 0; n < 8; n++) An[n] = g_A[d * 8 + n];
    __syncthreads();
    const float* bc = g_BC + (long)b * LQ * 16;

    float a[8], hh[8];
#pragma unroll
    for (int n = 0; n < 8; n++) { a[n] = 1.f; hh[n] = 0.f; }
    int base = tid * 16;
    for (int i = 0; i < 16; i++) {
        int l = base + i;
        float delta = sDelta[l];
        float du = delta * sU[l];
        const float4* bc4 = (const float4*)(bc + (long)l * 16);
        float4 b0 = bc4[0], b1 = bc4[1];
        float bl[8] = {b0.x,b0.y,b0.z,b0.w,b1.x,b1.y,b1.z,b1.w};
#pragma unroll
        for (int n = 0; n < 8; n++) {
            float p = __expf(delta * An[n]);
            hh[n] = p * hh[n] + du * bl[n];
            a[n] *= p;
        }
    }
#pragma unroll
    for (int n = 0; n < 8; n++) { sScan[n * 256 + tid] = a[n]; sScan[2048 + n * 256 + tid] = hh[n]; }
    __syncthreads();

    for (int off = 1; off < 256; off <<= 1) {
        float pa[8], pb[8];
        if (tid >= off) {
#pragma unroll
            for (int n = 0; n < 8; n++) {
                pa[n] = sScan[n * 256 + tid - off];
                pb[n] = sScan[2048 + n * 256 + tid - off];
            }
        }
        __syncthreads();
        if (tid >= off) {
#pragma unroll
            for (int n = 0; n < 8; n++) {
                float a2 = sScan[n * 256 + tid];
                float b2 = sScan[2048 + n * 256 + tid];
                sScan[n * 256 + tid] = pa[n] * a2;
                sScan[2048 + n * 256 + tid] = a2 * pb[n] + b2;
            }
        }
        __syncthreads();
    }
    float h0[8];
#pragma unroll
    for (int n = 0; n < 8; n++) h0[n] = (tid == 0) ? 0.f : sScan[2048 + n * 256 + tid - 1];
    __syncthreads();

    float Dd = Ds[d];
    for (int i = 0; i < 16; i++) {
        int l = base + i;
        float delta = sDelta[l];
        float u = sU[l];
        float du = delta * u;
        const float4* bc4 = (const float4*)(bc + (long)l * 16);
        float4 b0 = bc4[0], b1 = bc4[1], c0 = bc4[2], c1 = bc4[3];
        float bl[8] = {b0.x,b0.y,b0.z,b0.w,b1.x,b1.y,b1.z,b1.w};
        float cl[8] = {c0.x,c0.y,c0.z,c0.w,c1.x,c1.y,c1.z,c1.w};
        float y = Dd * u;
#pragma unroll
        for (int n = 0; n < 8; n++) {
            float p = __expf(delta * An[n]);
            h0[n] = p * h0[n] + du * bl[n];
            y += h0[n] * cl[n];
        }
        sScan[l] = y;
    }
    __syncthreads();
    float* yo = g_y + ((long)b * 192 + d) * LQ;
    for (int e = tid; e < LQ; e += 256) yo[e] = sScan[e];
}

// ---------------- LayerNorm + silu(z) gate ----------------
__global__ void ln_kernel(const float* __restrict__ gamma, const float* __restrict__ beta)
{
    __shared__ float sg[192], sb2[192];
    int tid = threadIdx.x;
    for (int e = tid; e < 192; e += 256) { sg[e] = gamma[e]; sb2[e] = beta[e]; }
    __syncthreads();
    int l = blockIdx.x * 256 + tid;
    int b = blockIdx.y;
    const float* yp = g_y + (long)b * 192 * LQ + l;
    float s = 0.f, ss = 0.f;
    for (int dd = 0; dd < 192; dd++) {
        float v = yp[(long)dd * LQ];
        s += v; ss += v * v;
    }
    float mu = s * (1.f / 192.f);
    float var = ss * (1.f / 192.f) - mu * mu;
    float rs = rsqrtf(var + 1e-5f);
    const float* zp = g_zsil + (long)b * 192 * LQ + l;
    float* op = g_yn + (long)b * 192 * LQ + l;
    for (int dd = 0; dd < 192; dd++) {
        float v = (yp[(long)dd * LQ] - mu) * rs * sg[dd] + sb2[dd];
        op[(long)dd * LQ] = v * zp[(long)dd * LQ];
    }
}

// ---------------- host launcher ----------------
extern "C" void kernel_launch(void* const* d_in, const int* in_sizes, int n_in,
                              void* d_out, int out_size)
{
    const float* x        = (const float*)d_in[0];
    const float* W_in     = (const float*)d_in[1];
    const float* W_dwc_i  = (const float*)d_in[2];
    const float* b_dwc_i  = (const float*)d_in[3];
    const float* W_dw3    = (const float*)d_in[4];
    const float* b_dw3    = (const float*)d_in[5];
    const float* W_dw5    = (const float*)d_in[6];
    const float* b_dw5    = (const float*)d_in[7];
    const float* W_dw7    = (const float*)d_in[8];
    const float* b_dw7    = (const float*)d_in[9];
    const float* W_dwc_f  = (const float*)d_in[10];
    const float* b_dwc_f  = (const float*)d_in[11];
    const float* W_conv2d = (const float*)d_in[12];
    const float* b_conv2d = (const float*)d_in[13];
    const float* W_haar   = (const float*)d_in[14];
    const float* x_proj_w = (const float*)d_in[15];
    const float* W_xconv  = (const float*)d_in[16];
    const float* b_xconv  = (const float*)d_in[17];
    const float* dt_w     = (const float*)d_in[18];
    const float* dt_b     = (const float*)d_in[19];
    const float* A_logs   = (const float*)d_in[20];
    const float* Ds       = (const float*)d_in[21];
    const float* ln_g     = (const float*)d_in[22];
    const float* ln_b     = (const float*)d_in[23];
    const float* W_out    = (const float*)d_in[24];
    float* out = (float*)d_out;

    float *p_xz, *p_t, *p_t2, *p_zf, *p_xc, *p_xdbl, *p_yn;
    cudaGetSymbolAddress((void**)&p_xz, g_xz);
    cudaGetSymbolAddress((void**)&p_t, g_t);
    cudaGetSymbolAddress((void**)&p_t2, g_t2);
    cudaGetSymbolAddress((void**)&p_zf, g_zf);
    cudaGetSymbolAddress((void**)&p_xc, g_xc);
    cudaGetSymbolAddress((void**)&p_xdbl, g_xdbl);
    cudaGetSymbolAddress((void**)&p_yn, g_yn);

    const int SMEM_SPLIT = (2*64*36 + 2*32*136) * 4;  // 53248
    const int SMEM_PLAIN = (64*36 + 32*136) * 4;      // 26624
    cudaFuncSetAttribute(gemm_tf32_kernel<true>,
                         cudaFuncAttributeMaxDynamicSharedMemorySize, SMEM_SPLIT);
    cudaFuncSetAttribute(gemm_tf32_kernel<false>,
                         cudaFuncAttributeMaxDynamicSharedMemorySize, SMEM_PLAIN);
    cudaFuncSetAttribute(haar_kernel, cudaFuncAttributeMaxDynamicSharedMemorySize, 73728);
    cudaFuncSetAttribute(scan_kernel, cudaFuncAttributeMaxDynamicSharedMemorySize, 49152);

    prep_kernel<<<6, 256>>>(A_logs);

    // K1: input GEMM x[b,96,L] -> xz[b,384,L] (split tf32, ~fp32 accuracy)
    gemm_tf32_kernel<true><<<dim3(32, 6, NB), 256, SMEM_SPLIT>>>(
        x, 96L * LQ, W_in, nullptr, p_xz, 384L * LQ, 384, 96);
    // K2: z branch 1x1 init conv (K=192 -> 384), plain tf32
    gemm_tf32_kernel<false><<<dim3(32, 6, NB), 256, SMEM_PLAIN>>>(
        p_xz + 192L * LQ, 384L * LQ, W_dwc_i, b_dwc_i, p_t, 384L * LQ, 384, 192);
    // K3: multi-scale depthwise + gelu
    gelu_copy_kernel<<<(int)((long)NB * 96 * LQ / 256), 256>>>();
    dwconv_gelu_kernel<3><<<dim3(96, NB), 256>>>(W_dw3, b_dw3, 96);
    dwconv_gelu_kernel<5><<<dim3(96, NB), 256>>>(W_dw5, b_dw5, 192);
    dwconv_gelu_kernel<7><<<dim3(96, NB), 256>>>(W_dw7, b_dw7, 288);
    // K4: z branch final 1x1 conv (K=384 -> 192), plain tf32
    gemm_tf32_kernel<false><<<dim3(32, 3, NB), 256, SMEM_PLAIN>>>(
        p_t2, 384L * LQ, W_dwc_f, b_dwc_f, p_zf, 192L * LQ, 192, 384);
    // K4b: transpose + silu gate
    ztrans_kernel<<<dim3(2, 2, NB * 192), dim3(32, 8)>>>();
    // K5: x branch depthwise 3x3 + silu
    dw3_silu_kernel<<<dim3(192, NB), 256>>>(W_conv2d, b_conv2d);
    // K6: haar -> yL, y_mean
    haar_kernel<<<dim3(32, NB), 256, 73728>>>(W_haar);
    // K7a: x_proj GEMM (K=192 -> 22), split tf32
    gemm_tf32_kernel<true><<<dim3(32, 1, NB), 256, SMEM_SPLIT>>>(
        p_xc, 192L * LQ, x_proj_w, nullptr, p_xdbl, 22L * LQ, 22, 192);
    // K7b: depthwise conv1d k=7
    conv1d_kernel<<<dim3(16, NB * 22), 256>>>(W_xconv, b_xconv);
    // K7c: dt projection + softplus
    dtproj_kernel<<<dim3(16, NB), 256>>>(dt_w, dt_b);
    // K7d: Bs/Cs assembly
    bc_kernel<<<dim3(16, NB), 256>>>();
    // K8: selective scan
    scan_kernel<<<NB * 192, 256, 49152>>>(Ds);
    // K9a: layernorm + gate
    ln_kernel<<<dim3(16, NB), 256>>>(ln_g, ln_b);
    // K9b: output GEMM (K=192 -> 96) into d_out, split tf32
    gemm_tf32_kernel<true><<<dim3(32, 2, NB), 256, SMEM_SPLIT>>>(
        p_yn, 192L * LQ, W_out, nullptr, out, 96L * LQ, 96, 192);
    (void)in_sizes; (void)n_in; (void)out_size;
}

// round 7
// speedup vs baseline: 2.0501x; 1.0907x over previous
#include <cuda_runtime.h>
#include <cuda_bf16.h>
#include <stdint.h>
#include <math.h>

#define NB 8
#define LQ 4096

// ---------------- device scratch (zero-init BSS, no allocation) ----------------
__device__ float g_xz   [(long)NB*384*LQ];
__device__ float g_t    [(long)NB*384*LQ];   // channels 96..383 used (0..95 go straight to g_t2)
__device__ float g_t2   [(long)NB*384*LQ];
__device__ float g_zsil [(long)NB*192*LQ];
__device__ float g_xc   [(long)NB*192*LQ];
__device__ float g_yL   [(long)NB*8*LQ];
__device__ float g_ym   [(long)NB*8*LQ];
__device__ float g_xdbl [(long)NB*22*LQ];
__device__ float g_delta[(long)NB*192*LQ];
__device__ float g_BC   [(long)NB*LQ*16];
__device__ float g_y    [(long)NB*192*LQ];
__device__ float g_yn   [(long)NB*192*LQ];
__device__ float g_A    [192*8];

// ---------------- prep: materialize A ----------------
__global__ void prep_kernel(const float* __restrict__ Alogs)
{
    int t = blockIdx.x * 256 + threadIdx.x;
    if (t < 192*8) g_A[t] = -expf(Alogs[t]);
}

__device__ __forceinline__ float gelu_exact(float v)
{
    return 0.5f * v * (1.f + erff(v * 0.70710678118654752f));
}

// ---------------- tf32 tensor-core GEMM (optional split + fused epilogues) -----------
// O[n][m] = bias[n] + sum_k Act[k][m] * W[n][k]
// EPI: 0 = plain store to O
//      1 = n<96 -> gelu into O2; else plain into O          (K2)
//      2 = silu + spatial transpose (l = h*64+w -> w*64+h)  (K4)
__device__ __forceinline__ uint32_t f2tf32(float f)
{
    uint32_t o;
    asm("cvt.rna.tf32.f32 %0, %1;" : "=r"(o) : "f"(f));
    return o;
}

__device__ __forceinline__ void mma_tf32(float* d, const uint32_t* a, const uint32_t* b)
{
    asm volatile("mma.sync.aligned.m16n8k8.row.col.f32.tf32.tf32.f32 "
                 "{%0,%1,%2,%3}, {%4,%5,%6,%7}, {%8,%9}, {%0,%1,%2,%3};"
                 : "+f"(d[0]), "+f"(d[1]), "+f"(d[2]), "+f"(d[3])
                 : "r"(a[0]), "r"(a[1]), "r"(a[2]), "r"(a[3]),
                   "r"(b[0]), "r"(b[1]));
}

__device__ __forceinline__ void epi_store(float* Ob, float* O2b, int n, int m, float v, int EPI)
{
    if (EPI == 1) {
        if (n < 96) O2b[(long)n * LQ + m] = gelu_exact(v);
        else        Ob [(long)n * LQ + m] = v;
    } else if (EPI == 2) {
        int tr = ((m & 63) << 6) | (m >> 6);
        Ob[(long)n * LQ + tr] = v / (1.f + __expf(-v));
    } else {
        Ob[(long)n * LQ + m] = v;
    }
}

template<bool SPLIT, int EPI>
__global__ void __launch_bounds__(256)
gemm_tf32_kernel(const float* __restrict__ Act, long actStride,
                 const float* __restrict__ W, const float* __restrict__ bias,
                 float* __restrict__ O, float* __restrict__ O2,
                 long oStride, int N, int K)
{
    extern __shared__ uint32_t dsm[];
    uint32_t* sWb = dsm;
    uint32_t* sWs = SPLIT ? (dsm + 64*36) : dsm;
    uint32_t* sAb = dsm + (SPLIT ? 2 : 1) * 64*36;
    uint32_t* sAs = SPLIT ? (sAb + 32*136) : sAb;

    const float* Ab = Act + (long)blockIdx.z * actStride;
    float* Ob = O + (long)blockIdx.z * oStride;
    float* O2b = O2 ? (O2 + (long)blockIdx.z * oStride) : nullptr;
    int m0 = blockIdx.x * 128, n0 = blockIdx.y * 64;
    int tid = threadIdx.x, lane = tid & 31, wid = tid >> 5;
    int wn = (wid & 1) * 32;
    int wm = (wid >> 1) * 32;

    float d[2][4][4];
#pragma unroll
    for (int i = 0; i < 2; i++)
#pragma unroll
        for (int j = 0; j < 4; j++)
#pragma unroll
            for (int q = 0; q < 4; q++) d[i][j][q] = 0.f;

    for (int kc = 0; kc < K; kc += 32) {
#pragma unroll
        for (int i = 0; i < 2; i++) {
            int e = tid + i * 256;
            int row = e >> 3, c4 = (e & 7) * 4;
            int n = n0 + row;
            float4 v = make_float4(0.f, 0.f, 0.f, 0.f);
            if (n < N) v = *(const float4*)(W + (long)n * K + kc + c4);
            float vv[4] = {v.x, v.y, v.z, v.w};
#pragma unroll
            for (int t = 0; t < 4; t++) {
                uint32_t bg = f2tf32(vv[t]);
                sWb[row * 36 + c4 + t] = bg;
                if constexpr (SPLIT)
                    sWs[row * 36 + c4 + t] = f2tf32(vv[t] - __uint_as_float(bg));
            }
        }
#pragma unroll
        for (int i = 0; i < 4; i++) {
            int e = tid + i * 256;
            int row = e >> 5, c4 = (e & 31) * 4;
            float4 v = *(const float4*)(Ab + (long)(kc + row) * LQ + m0 + c4);
            float vv[4] = {v.x, v.y, v.z, v.w};
#pragma unroll
            for (int t = 0; t < 4; t++) {
                uint32_t bg = f2tf32(vv[t]);
                sAb[row * 136 + c4 + t] = bg;
                if constexpr (SPLIT)
                    sAs[row * 136 + c4 + t] = f2tf32(vv[t] - __uint_as_float(bg));
            }
        }
        __syncthreads();

#pragma unroll
        for (int ks = 0; ks < 4; ks++) {
            int kk = ks * 8;
            uint32_t afrB[2][4], bfrB[4][2];
            uint32_t afrS[2][4], bfrS[4][2];
            int r = wn + (lane >> 2);
            int c = kk + (lane & 3);
#pragma unroll
            for (int i = 0; i < 2; i++) {
                int rb = r + i * 16;
                afrB[i][0] = sWb[rb * 36 + c];
                afrB[i][1] = sWb[(rb + 8) * 36 + c];
                afrB[i][2] = sWb[rb * 36 + c + 4];
                afrB[i][3] = sWb[(rb + 8) * 36 + c + 4];
                if constexpr (SPLIT) {
                    afrS[i][0] = sWs[rb * 36 + c];
                    afrS[i][1] = sWs[(rb + 8) * 36 + c];
                    afrS[i][2] = sWs[rb * 36 + c + 4];
                    afrS[i][3] = sWs[(rb + 8) * 36 + c + 4];
                }
            }
            int mcol = wm + (lane >> 2);
            int krow = kk + (lane & 3);
#pragma unroll
            for (int j = 0; j < 4; j++) {
                bfrB[j][0] = sAb[krow * 136 + mcol + j * 8];
                bfrB[j][1] = sAb[(krow + 4) * 136 + mcol + j * 8];
                if constexpr (SPLIT) {
                    bfrS[j][0] = sAs[krow * 136 + mcol + j * 8];
                    bfrS[j][1] = sAs[(krow + 4) * 136 + mcol + j * 8];
                }
            }
#pragma unroll
            for (int i = 0; i < 2; i++)
#pragma unroll
                for (int j = 0; j < 4; j++) {
                    if constexpr (SPLIT) {
                        mma_tf32(d[i][j], afrB[i], bfrS[j]);
                        mma_tf32(d[i][j], afrS[i], bfrB[j]);
                    }
                    mma_tf32(d[i][j], afrB[i], bfrB[j]);
                }
        }
        __syncthreads();
    }

#pragma unroll
    for (int i = 0; i < 2; i++) {
        int n = n0 + wn + i * 16 + (lane >> 2);
        float bb0 = (bias && n < N) ? bias[n] : 0.f;
        float bb1 = (bias && n + 8 < N) ? bias[n + 8] : 0.f;
#pragma unroll
        for (int j = 0; j < 4; j++) {
            int m = m0 + wm + j * 8 + 2 * (lane & 3);
            if (n < N) {
                epi_store(Ob, O2b, n, m,     d[i][j][0] + bb0, EPI);
                epi_store(Ob, O2b, n, m + 1, d[i][j][1] + bb0, EPI);
            }
            if (n + 8 < N) {
                epi_store(Ob, O2b, n + 8, m,     d[i][j][2] + bb1, EPI);
                epi_store(Ob, O2b, n + 8, m + 1, d[i][j][3] + bb1, EPI);
            }
        }
    }
}

// ---------------- z branch: smem-tiled depthwise conv + exact GELU ----
template<int KSZ>
__global__ void dwconv_gelu_kernel(const float* __restrict__ W, const float* __restrict__ bias,
                                   int coBase)
{
    constexpr int PAD = KSZ / 2;
    constexpr int SH = 64 + 2 * PAD;
    __shared__ float sm[SH * 72];
    int c = blockIdx.x;
    int b = blockIdx.y;
    int co = coBase + c;
    int tid = threadIdx.x;
    const float* src = g_t + ((long)b * 384 + co) * LQ;

    for (int e = tid; e < SH * 72; e += 256) sm[e] = 0.f;
    __syncthreads();
    for (int e = tid; e < LQ; e += 256) {
        int h = e >> 6, w = e & 63;
        sm[(h + PAD) * 72 + (w + PAD)] = src[e];
    }
    __syncthreads();

    float wreg[KSZ * KSZ];
#pragma unroll
    for (int i = 0; i < KSZ * KSZ; i++) wreg[i] = W[c * KSZ * KSZ + i];
    float bb = bias[c];

    float* dst = g_t2 + ((long)b * 384 + co) * LQ;
    for (int e = tid; e < LQ; e += 256) {
        int h = e >> 6, w = e & 63;
        float acc = bb;
#pragma unroll
        for (int ky = 0; ky < KSZ; ky++) {
            const float* row = sm + (h + ky) * 72 + w;
#pragma unroll
            for (int kx = 0; kx < KSZ; kx++)
                acc += row[kx] * wreg[ky * KSZ + kx];
        }
        dst[e] = gelu_exact(acc);
    }
}

// ---------------- x branch: depthwise 3x3 + bias + silu ----------------
__global__ void dw3_silu_kernel(const float* __restrict__ W, const float* __restrict__ bias)
{
    __shared__ float sm[66 * 68];
    int c = blockIdx.x;
    int b = blockIdx.y;
    int tid = threadIdx.x;
    const float* src = g_xz + ((long)b * 384 + c) * LQ;
    for (int e = tid; e < 66 * 68; e += 256) sm[e] = 0.f;
    __syncthreads();
    for (int e = tid; e < LQ; e += 256) {
        int h = e >> 6, w = e & 63;
        sm[(h + 1) * 68 + (w + 1)] = src[e];
    }
    __syncthreads();
    float w0 = W[c*9+0], w1 = W[c*9+1], w2 = W[c*9+2];
    float w3 = W[c*9+3], w4 = W[c*9+4], w5 = W[c*9+5];
    float w6 = W[c*9+6], w7 = W[c*9+7], w8 = W[c*9+8];
    float bb = bias[c];
    float* dst = g_xc + ((long)b * 192 + c) * LQ;
    for (int e = tid; e < LQ; e += 256) {
        int h = e >> 6, w = e & 63;
        const float* r0 = sm + h * 68 + w;
        float acc = bb + r0[0]*w0 + r0[1]*w1 + r0[2]*w2
                       + r0[68]*w3 + r0[69]*w4 + r0[70]*w5
                       + r0[136]*w6 + r0[137]*w7 + r0[138]*w8;
        dst[e] = acc / (1.f + __expf(-acc));
    }
}

// ---------------- haar 1x1 conv + strided combine -> yL, y_mean ----------------
__global__ void haar_kernel(const float* __restrict__ Wh)
{
    extern __shared__ float smh[];
    float* sW = smh;
    float* s1 = smh + 32 * 192;
    float* s2 = s1 + 192 * 32;
    int i = blockIdx.x, b = blockIdx.y;
    int tid = threadIdx.x;
    for (int e = tid; e < 32 * 192; e += 256) sW[e] = Wh[e];
    const float* xcb = g_xc + (long)b * 192 * LQ;
    for (int e = tid; e < 192 * 32; e += 256) {
        int d = e >> 5, j = e & 31;
        const float* row0 = xcb + (long)d * LQ + (2 * i) * 64 + 2 * j;
        float xa = row0[0], xb = row0[1];
        float xc2 = row0[64], xd = row0[65];
        s1[d * 32 + j] = xa + xb + xc2 + xd;
        s2[d * 32 + j] = 3.f * xa - xb - xc2 - xd;
    }
    __syncthreads();
    for (int e = tid; e < 2048; e += 256) {
        int which = e >> 10;
        int ch = (e >> 5) & 31;
        int j = e & 31;
        const float* sv = (which ? s2 : s1) + j;
        const float* wr = sW + ch * 192;
        float acc = 0.f;
#pragma unroll 4
        for (int d = 0; d < 192; d++) acc += wr[d] * sv[d * 32];
        acc *= which ? (1.f / 6.f) : 0.5f;
        int n = ch >> 2;
        int lpos = (ch & 3) * 1024 + i * 32 + j;
        float* dst = which ? g_ym : g_yL;
        dst[((long)b * 8 + n) * LQ + lpos] = acc;
    }
}

// ---------------- fused: conv1d(k=7) + dt projection + softplus + B/C assembly --------
__global__ void convdtbc_kernel(const float* __restrict__ Wx, const float* __restrict__ bx,
                                const float* __restrict__ Wdt, const float* __restrict__ dtb)
{
    __shared__ float sIn[22][264];   // channels x (256 + 6 halo + pad)
    __shared__ float sWd[192 * 6];
    __shared__ float sBd[192];
    __shared__ float sWc[22 * 7];
    __shared__ float sbc[22];
    int tid = threadIdx.x;
    int l0 = blockIdx.x * 256;
    int b = blockIdx.y;

    for (int e = tid; e < 1152; e += 256) sWd[e] = Wdt[e];
    for (int e = tid; e < 192; e += 256) sBd[e] = dtb[e];
    for (int e = tid; e < 154; e += 256) sWc[e] = Wx[e];
    for (int e = tid; e < 22; e += 256) sbc[e] = bx[e];
    // stage input: 22 channels x [l0-3, l0+259)
    for (int e = tid; e < 22 * 262; e += 256) {
        int c = e / 262, p = e % 262;
        int l = l0 + p - 3;
        float v = 0.f;
        if ((unsigned)l < (unsigned)LQ) v = g_xdbl[((long)b * 22 + c) * LQ + l];
        sIn[c][p] = v;
    }
    __syncthreads();

    int l = l0 + tid;
    // conv1d for all 22 channels
    float r[22];
#pragma unroll
    for (int c = 0; c < 22; c++) {
        float acc = sbc[c];
#pragma unroll
        for (int k = 0; k < 7; k++) acc += sIn[c][tid + k] * sWc[c * 7 + k];
        r[c] = acc;
    }
    // dt projection + softplus -> delta
    float* dout = g_delta + (long)b * 192 * LQ + l;
    for (int d = 0; d < 192; d++) {
        float s = sBd[d];
#pragma unroll
        for (int rr = 0; rr < 6; rr++) s += sWd[d * 6 + rr] * r[rr];
        float sp = (s > 20.f) ? s : log1pf(expf(s));
        dout[(long)d * LQ] = sp;
    }
    // B/C assembly
    float* o = g_BC + ((long)b * LQ + l) * 16;
    float4 v0, v1, v2, v3;
    float bs[8], cs[8];
#pragma unroll
    for (int n = 0; n < 8; n++) {
        bs[n] = r[6 + n]  * g_yL[((long)b * 8 + n) * LQ + l] + 1e-6f;
        cs[n] = r[14 + n] * g_ym[((long)b * 8 + n) * LQ + l] + 1e-6f;
    }
    v0 = make_float4(bs[0], bs[1], bs[2], bs[3]);
    v1 = make_float4(bs[4], bs[5], bs[6], bs[7]);
    v2 = make_float4(cs[0], cs[1], cs[2], cs[3]);
    v3 = make_float4(cs[4], cs[5], cs[6], cs[7]);
    ((float4*)o)[0] = v0; ((float4*)o)[1] = v1;
    ((float4*)o)[2] = v2; ((float4*)o)[3] = v3;
}

// ---------------- selective scan ----------------
__global__ void scan_kernel(const float* __restrict__ Ds)
{
    extern __shared__ float sm[];
    float* sDelta = sm;
    float* sU = sm + 4096;
    float* sScan = sm + 8192;
    int bd = blockIdx.x;
    int b = bd / 192, d = bd % 192;
    int tid = threadIdx.x;
    const float* dp = g_delta + ((long)b * 192 + d) * LQ;
    const float* up = g_xc    + ((long)b * 192 + d) * LQ;
    for (int e = tid; e < LQ; e += 256) { sDelta[e] = dp[e]; sU[e] = up[e]; }
    float An[8];
#pragma unroll
    for (int n = 0; n < 8; n++) An[n] = g_A[d * 8 + n];
    __syncthreads();
    const float* bc = g_BC + (long)b * LQ * 16;

    float a[8], hh[8];
#pragma unroll
    for (int n = 0; n < 8; n++) { a[n] = 1.f; hh[n] = 0.f; }
    int base = tid * 16;
    for (int i = 0; i < 16; i++) {
        int l = base + i;
        float delta = sDelta[l];
        float du = delta * sU[l];
        const float4* bc4 = (const float4*)(bc + (long)l * 16);
        float4 b0 = bc4[0], b1 = bc4[1];
        float bl[8] = {b0.x,b0.y,b0.z,b0.w,b1.x,b1.y,b1.z,b1.w};
#pragma unroll
        for (int n = 0; n < 8; n++) {
            float p = __expf(delta * An[n]);
            hh[n] = p * hh[n] + du * bl[n];
            a[n] *= p;
        }
    }
#pragma unroll
    for (int n = 0; n < 8; n++) { sScan[n * 256 + tid] = a[n]; sScan[2048 + n * 256 + tid] = hh[n]; }
    __syncthreads();

    for (int off = 1; off < 256; off <<= 1) {
        float pa[8], pb[8];
        if (tid >= off) {
#pragma unroll
            for (int n = 0; n < 8; n++) {
                pa[n] = sScan[n * 256 + tid - off];
                pb[n] = sScan[2048 + n * 256 + tid - off];
            }
        }
        __syncthreads();
        if (tid >= off) {
#pragma unroll
            for (int n = 0; n < 8; n++) {
                float a2 = sScan[n * 256 + tid];
                float b2 = sScan[2048 + n * 256 + tid];
                sScan[n * 256 + tid] = pa[n] * a2;
                sScan[2048 + n * 256 + tid] = a2 * pb[n] + b2;
            }
        }
        __syncthreads();
    }
    float h0[8];
#pragma unroll
    for (int n = 0; n < 8; n++) h0[n] = (tid == 0) ? 0.f : sScan[2048 + n * 256 + tid - 1];
    __syncthreads();

    float Dd = Ds[d];
    for (int i = 0; i < 16; i++) {
        int l = base + i;
        float delta = sDelta[l];
        float u = sU[l];
        float du = delta * u;
        const float4* bc4 = (const float4*)(bc + (long)l * 16);
        float4 b0 = bc4[0], b1 = bc4[1], c0 = bc4[2], c1 = bc4[3];
        float bl[8] = {b0.x,b0.y,b0.z,b0.w,b1.x,b1.y,b1.z,b1.w};
        float cl[8] = {c0.x,c0.y,c0.z,c0.w,c1.x,c1.y,c1.z,c1.w};
        float y = Dd * u;
#pragma unroll
        for (int n = 0; n < 8; n++) {
            float p = __expf(delta * An[n]);
            h0[n] = p * h0[n] + du * bl[n];
            y += h0[n] * cl[n];
        }
        sScan[l] = y;
    }
    __syncthreads();
    float* yo = g_y + ((long)b * 192 + d) * LQ;
    for (int e = tid; e < LQ; e += 256) yo[e] = sScan[e];
}

// ---------------- LayerNorm + silu(z) gate ----------------
__global__ void ln_kernel(const float* __restrict__ gamma, const float* __restrict__ beta)
{
    __shared__ float sg[192], sb2[192];
    int tid = threadIdx.x;
    for (int e = tid; e < 192; e += 256) { sg[e] = gamma[e]; sb2[e] = beta[e]; }
    __syncthreads();
    int l = blockIdx.x * 256 + tid;
    int b = blockIdx.y;
    const float* yp = g_y + (long)b * 192 * LQ + l;
    float s = 0.f, ss = 0.f;
    for (int dd = 0; dd < 192; dd++) {
        float v = yp[(long)dd * LQ];
        s += v; ss += v * v;
    }
    float mu = s * (1.f / 192.f);
    float var = ss * (1.f / 192.f) - mu * mu;
    float rs = rsqrtf(var + 1e-5f);
    const float* zp = g_zsil + (long)b * 192 * LQ + l;
    float* op = g_yn + (long)b * 192 * LQ + l;
    for (int dd = 0; dd < 192; dd++) {
        float v = (yp[(long)dd * LQ] - mu) * rs * sg[dd] + sb2[dd];
        op[(long)dd * LQ] = v * zp[(long)dd * LQ];
    }
}

// ---------------- host launcher ----------------
extern "C" void kernel_launch(void* const* d_in, const int* in_sizes, int n_in,
                              void* d_out, int out_size)
{
    const float* x        = (const float*)d_in[0];
    const float* W_in     = (const float*)d_in[1];
    const float* W_dwc_i  = (const float*)d_in[2];
    const float* b_dwc_i  = (const float*)d_in[3];
    const float* W_dw3    = (const float*)d_in[4];
    const float* b_dw3    = (const float*)d_in[5];
    const float* W_dw5    = (const float*)d_in[6];
    const float* b_dw5    = (const float*)d_in[7];
    const float* W_dw7    = (const float*)d_in[8];
    const float* b_dw7    = (const float*)d_in[9];
    const float* W_dwc_f  = (const float*)d_in[10];
    const float* b_dwc_f  = (const float*)d_in[11];
    const float* W_conv2d = (const float*)d_in[12];
    const float* b_conv2d = (const float*)d_in[13];
    const float* W_haar   = (const float*)d_in[14];
    const float* x_proj_w = (const float*)d_in[15];
    const float* W_xconv  = (const float*)d_in[16];
    const float* b_xconv  = (const float*)d_in[17];
    const float* dt_w     = (const float*)d_in[18];
    const float* dt_b     = (const float*)d_in[19];
    const float* A_logs   = (const float*)d_in[20];
    const float* Ds       = (const float*)d_in[21];
    const float* ln_g     = (const float*)d_in[22];
    const float* ln_b     = (const float*)d_in[23];
    const float* W_out    = (const float*)d_in[24];
    float* out = (float*)d_out;

    float *p_xz, *p_t, *p_t2, *p_zsil, *p_xc, *p_xdbl, *p_yn;
    cudaGetSymbolAddress((void**)&p_xz, g_xz);
    cudaGetSymbolAddress((void**)&p_t, g_t);
    cudaGetSymbolAddress((void**)&p_t2, g_t2);
    cudaGetSymbolAddress((void**)&p_zsil, g_zsil);
    cudaGetSymbolAddress((void**)&p_xc, g_xc);
    cudaGetSymbolAddress((void**)&p_xdbl, g_xdbl);
    cudaGetSymbolAddress((void**)&p_yn, g_yn);

    const int SMEM_SPLIT = (2*64*36 + 2*32*136) * 4;
    const int SMEM_PLAIN = (64*36 + 32*136) * 4;
    cudaFuncSetAttribute((const void*)gemm_tf32_kernel<true, 0>,
                         cudaFuncAttributeMaxDynamicSharedMemorySize, SMEM_SPLIT);
    cudaFuncSetAttribute((const void*)gemm_tf32_kernel<false, 1>,
                         cudaFuncAttributeMaxDynamicSharedMemorySize, SMEM_PLAIN);
    cudaFuncSetAttribute((const void*)gemm_tf32_kernel<false, 2>,
                         cudaFuncAttributeMaxDynamicSharedMemorySize, SMEM_PLAIN);
    cudaFuncSetAttribute(haar_kernel, cudaFuncAttributeMaxDynamicSharedMemorySize, 73728);
    cudaFuncSetAttribute(scan_kernel, cudaFuncAttributeMaxDynamicSharedMemorySize, 49152);

    // one-time stream/event setup (first call is NOT graph-captured)
    static cudaStream_t sZ = nullptr;
    static cudaEvent_t evFork = nullptr, evJoin = nullptr;
    if (!sZ) {
        cudaStreamCreateWithFlags(&sZ, cudaStreamNonBlocking);
        cudaEventCreateWithFlags(&evFork, cudaEventDisableTiming);
        cudaEventCreateWithFlags(&evJoin, cudaEventDisableTiming);
    }

    prep_kernel<<<6, 256>>>(A_logs);

    // K1: input GEMM x[b,96,L] -> xz[b,384,L] (split tf32 ~ fp32 accuracy)
    gemm_tf32_kernel<true, 0><<<dim3(32, 6, NB), 256, SMEM_SPLIT>>>(
        x, 96L * LQ, W_in, nullptr, p_xz, nullptr, 384L * LQ, 384, 96);

    // ---- fork: z branch on stream sZ ----
    cudaEventRecord(evFork, 0);
    cudaStreamWaitEvent(sZ, evFork, 0);

    // K2: z 1x1 init conv (192->384), gelu fused for n<96 straight into g_t2
    gemm_tf32_kernel<false, 1><<<dim3(32, 6, NB), 256, SMEM_PLAIN, sZ>>>(
        p_xz + 192L * LQ, 384L * LQ, W_dwc_i, b_dwc_i, p_t, p_t2, 384L * LQ, 384, 192);
    dwconv_gelu_kernel<3><<<dim3(96, NB), 256, 0, sZ>>>(W_dw3, b_dw3, 96);
    dwconv_gelu_kernel<5><<<dim3(96, NB), 256, 0, sZ>>>(W_dw5, b_dw5, 192);
    dwconv_gelu_kernel<7><<<dim3(96, NB), 256, 0, sZ>>>(W_dw7, b_dw7, 288);
    // K4: z final 1x1 conv (384->192), silu+transpose fused, writes g_zsil
    gemm_tf32_kernel<false, 2><<<dim3(32, 3, NB), 256, SMEM_PLAIN, sZ>>>(
        p_t2, 384L * LQ, W_dwc_f, b_dwc_f, p_zsil, nullptr, 192L * LQ, 192, 384);
    cudaEventRecord(evJoin, sZ);

    // ---- x branch on default stream ----
    dw3_silu_kernel<<<dim3(192, NB), 256>>>(W_conv2d, b_conv2d);
    haar_kernel<<<dim3(32, NB), 256, 73728>>>(W_haar);
    // K7a: x_proj GEMM (192 -> 22), split tf32
    gemm_tf32_kernel<true, 0><<<dim3(32, 1, NB), 256, SMEM_SPLIT>>>(
        p_xc, 192L * LQ, x_proj_w, nullptr, p_xdbl, nullptr, 22L * LQ, 22, 192);
    // fused conv1d + dtproj + BC
    convdtbc_kernel<<<dim3(16, NB), 256>>>(W_xconv, b_xconv, dt_w, dt_b);
    // selective scan
    scan_kernel<<<NB * 192, 256, 49152>>>(Ds);

    // ---- join, then LN + output GEMM ----
    cudaStreamWaitEvent(0, evJoin, 0);
    ln_kernel<<<dim3(16, NB), 256>>>(ln_g, ln_b);
    gemm_tf32_kernel<true, 0><<<dim3(32, 2, NB), 256, SMEM_SPLIT>>>(
        p_yn, 192L * LQ, W_out, nullptr, out, nullptr, 96L * LQ, 96, 192);
    (void)in_sizes; (void)n_in; (void)out_size;
}

// round 8
// speedup vs baseline: 2.0510x; 1.0004x over previous
#include <cuda_runtime.h>
#include <cuda_bf16.h>
#include <stdint.h>
#include <math.h>

#define NB 8
#define LQ 4096

// ---------------- device scratch (zero-init BSS, no allocation) ----------------
__device__ float g_xz   [(long)NB*384*LQ];
__device__ float g_t    [(long)NB*384*LQ];
__device__ float g_t2   [(long)NB*384*LQ];
__device__ float g_zsil [(long)NB*192*LQ];
__device__ float g_xc   [(long)NB*192*LQ];
__device__ float g_yL   [(long)NB*8*LQ];
__device__ float g_ym   [(long)NB*8*LQ];
__device__ float g_xdbl [(long)NB*22*LQ];
__device__ float g_delta[(long)NB*192*LQ];
__device__ float g_BC   [(long)NB*LQ*16];
__device__ float g_y    [(long)NB*192*LQ];
__device__ float g_yn   [(long)NB*192*LQ];
__device__ float g_A    [192*8];
__device__ int   g_pow_ok;

// ---------------- prep: materialize A ----------------
__global__ void prep_kernel(const float* __restrict__ Alogs)
{
    int t = blockIdx.x * 256 + threadIdx.x;
    if (t < 192*8) g_A[t] = -expf(Alogs[t]);
}

// verify A[d][n] == A[d][0]*(n+1) (multiplicative power structure)
__global__ void prep2_kernel()
{
    __shared__ int ok;
    if (threadIdx.x == 0) ok = 1;
    __syncthreads();
    for (int d = threadIdx.x; d < 192; d += 256) {
        float a0 = g_A[d * 8];
        for (int n = 1; n < 8; n++) {
            float expect = a0 * (float)(n + 1);
            float got = g_A[d * 8 + n];
            if (fabsf(got - expect) > 1e-5f * fabsf(expect)) atomicAnd(&ok, 0);
        }
    }
    __syncthreads();
    if (threadIdx.x == 0) g_pow_ok = ok;
}

__device__ __forceinline__ float gelu_exact(float v)
{
    return 0.5f * v * (1.f + erff(v * 0.70710678118654752f));
}

// ---------------- tf32 tensor-core GEMM (optional split + fused epilogues) -----------
__device__ __forceinline__ uint32_t f2tf32(float f)
{
    uint32_t o;
    asm("cvt.rna.tf32.f32 %0, %1;" : "=r"(o) : "f"(f));
    return o;
}

__device__ __forceinline__ void mma_tf32(float* d, const uint32_t* a, const uint32_t* b)
{
    asm volatile("mma.sync.aligned.m16n8k8.row.col.f32.tf32.tf32.f32 "
                 "{%0,%1,%2,%3}, {%4,%5,%6,%7}, {%8,%9}, {%0,%1,%2,%3};"
                 : "+f"(d[0]), "+f"(d[1]), "+f"(d[2]), "+f"(d[3])
                 : "r"(a[0]), "r"(a[1]), "r"(a[2]), "r"(a[3]),
                   "r"(b[0]), "r"(b[1]));
}

__device__ __forceinline__ void epi_store(float* Ob, float* O2b, int n, int m, float v, int EPI)
{
    if (EPI == 1) {
        if (n < 96) O2b[(long)n * LQ + m] = gelu_exact(v);
        else        Ob [(long)n * LQ + m] = v;
    } else if (EPI == 2) {
        int tr = ((m & 63) << 6) | (m >> 6);
        Ob[(long)n * LQ + tr] = v / (1.f + __expf(-v));
    } else {
        Ob[(long)n * LQ + m] = v;
    }
}

template<bool SPLIT, int EPI>
__global__ void __launch_bounds__(256)
gemm_tf32_kernel(const float* __restrict__ Act, long actStride,
                 const float* __restrict__ W, const float* __restrict__ bias,
                 float* __restrict__ O, float* __restrict__ O2,
                 long oStride, int N, int K)
{
    extern __shared__ uint32_t dsm[];
    uint32_t* sWb = dsm;
    uint32_t* sWs = SPLIT ? (dsm + 64*36) : dsm;
    uint32_t* sAb = dsm + (SPLIT ? 2 : 1) * 64*36;
    uint32_t* sAs = SPLIT ? (sAb + 32*136) : sAb;

    const float* Ab = Act + (long)blockIdx.z * actStride;
    float* Ob = O + (long)blockIdx.z * oStride;
    float* O2b = O2 ? (O2 + (long)blockIdx.z * oStride) : nullptr;
    int m0 = blockIdx.x * 128, n0 = blockIdx.y * 64;
    int tid = threadIdx.x, lane = tid & 31, wid = tid >> 5;
    int wn = (wid & 1) * 32;
    int wm = (wid >> 1) * 32;

    float d[2][4][4];
#pragma unroll
    for (int i = 0; i < 2; i++)
#pragma unroll
        for (int j = 0; j < 4; j++)
#pragma unroll
            for (int q = 0; q < 4; q++) d[i][j][q] = 0.f;

    for (int kc = 0; kc < K; kc += 32) {
#pragma unroll
        for (int i = 0; i < 2; i++) {
            int e = tid + i * 256;
            int row = e >> 3, c4 = (e & 7) * 4;
            int n = n0 + row;
            float4 v = make_float4(0.f, 0.f, 0.f, 0.f);
            if (n < N) v = *(const float4*)(W + (long)n * K + kc + c4);
            float vv[4] = {v.x, v.y, v.z, v.w};
#pragma unroll
            for (int t = 0; t < 4; t++) {
                uint32_t bg = f2tf32(vv[t]);
                sWb[row * 36 + c4 + t] = bg;
                if constexpr (SPLIT)
                    sWs[row * 36 + c4 + t] = f2tf32(vv[t] - __uint_as_float(bg));
            }
        }
#pragma unroll
        for (int i = 0; i < 4; i++) {
            int e = tid + i * 256;
            int row = e >> 5, c4 = (e & 31) * 4;
            float4 v = *(const float4*)(Ab + (long)(kc + row) * LQ + m0 + c4);
            float vv[4] = {v.x, v.y, v.z, v.w};
#pragma unroll
            for (int t = 0; t < 4; t++) {
                uint32_t bg = f2tf32(vv[t]);
                sAb[row * 136 + c4 + t] = bg;
                if constexpr (SPLIT)
                    sAs[row * 136 + c4 + t] = f2tf32(vv[t] - __uint_as_float(bg));
            }
        }
        __syncthreads();

#pragma unroll
        for (int ks = 0; ks < 4; ks++) {
            int kk = ks * 8;
            uint32_t afrB[2][4], bfrB[4][2];
            uint32_t afrS[2][4], bfrS[4][2];
            int r = wn + (lane >> 2);
            int c = kk + (lane & 3);
#pragma unroll
            for (int i = 0; i < 2; i++) {
                int rb = r + i * 16;
                afrB[i][0] = sWb[rb * 36 + c];
                afrB[i][1] = sWb[(rb + 8) * 36 + c];
                afrB[i][2] = sWb[rb * 36 + c + 4];
                afrB[i][3] = sWb[(rb + 8) * 36 + c + 4];
                if constexpr (SPLIT) {
                    afrS[i][0] = sWs[rb * 36 + c];
                    afrS[i][1] = sWs[(rb + 8) * 36 + c];
                    afrS[i][2] = sWs[rb * 36 + c + 4];
                    afrS[i][3] = sWs[(rb + 8) * 36 + c + 4];
                }
            }
            int mcol = wm + (lane >> 2);
            int krow = kk + (lane & 3);
#pragma unroll
            for (int j = 0; j < 4; j++) {
                bfrB[j][0] = sAb[krow * 136 + mcol + j * 8];
                bfrB[j][1] = sAb[(krow + 4) * 136 + mcol + j * 8];
                if constexpr (SPLIT) {
                    bfrS[j][0] = sAs[krow * 136 + mcol + j * 8];
                    bfrS[j][1] = sAs[(krow + 4) * 136 + mcol + j * 8];
                }
            }
#pragma unroll
            for (int i = 0; i < 2; i++)
#pragma unroll
                for (int j = 0; j < 4; j++) {
                    if constexpr (SPLIT) {
                        mma_tf32(d[i][j], afrB[i], bfrS[j]);
                        mma_tf32(d[i][j], afrS[i], bfrB[j]);
                    }
                    mma_tf32(d[i][j], afrB[i], bfrB[j]);
                }
        }
        __syncthreads();
    }

#pragma unroll
    for (int i = 0; i < 2; i++) {
        int n = n0 + wn + i * 16 + (lane >> 2);
        float bb0 = (bias && n < N) ? bias[n] : 0.f;
        float bb1 = (bias && n + 8 < N) ? bias[n + 8] : 0.f;
#pragma unroll
        for (int j = 0; j < 4; j++) {
            int m = m0 + wm + j * 8 + 2 * (lane & 3);
            if (n < N) {
                epi_store(Ob, O2b, n, m,     d[i][j][0] + bb0, EPI);
                epi_store(Ob, O2b, n, m + 1, d[i][j][1] + bb0, EPI);
            }
            if (n + 8 < N) {
                epi_store(Ob, O2b, n + 8, m,     d[i][j][2] + bb1, EPI);
                epi_store(Ob, O2b, n + 8, m + 1, d[i][j][3] + bb1, EPI);
            }
        }
    }
}

// ---------------- z branch: smem-tiled depthwise conv + exact GELU ----
template<int KSZ>
__global__ void dwconv_gelu_kernel(const float* __restrict__ W, const float* __restrict__ bias,
                                   int coBase)
{
    constexpr int PAD = KSZ / 2;
    constexpr int SH = 64 + 2 * PAD;
    __shared__ float sm[SH * 72];
    int c = blockIdx.x;
    int b = blockIdx.y;
    int co = coBase + c;
    int tid = threadIdx.x;
    const float* src = g_t + ((long)b * 384 + co) * LQ;

    for (int e = tid; e < SH * 72; e += 256) sm[e] = 0.f;
    __syncthreads();
    for (int e = tid; e < LQ; e += 256) {
        int h = e >> 6, w = e & 63;
        sm[(h + PAD) * 72 + (w + PAD)] = src[e];
    }
    __syncthreads();

    float wreg[KSZ * KSZ];
#pragma unroll
    for (int i = 0; i < KSZ * KSZ; i++) wreg[i] = W[c * KSZ * KSZ + i];
    float bb = bias[c];

    float* dst = g_t2 + ((long)b * 384 + co) * LQ;
    for (int e = tid; e < LQ; e += 256) {
        int h = e >> 6, w = e & 63;
        float acc = bb;
#pragma unroll
        for (int ky = 0; ky < KSZ; ky++) {
            const float* row = sm + (h + ky) * 72 + w;
#pragma unroll
            for (int kx = 0; kx < KSZ; kx++)
                acc += row[kx] * wreg[ky * KSZ + kx];
        }
        dst[e] = gelu_exact(acc);
    }
}

// ---------------- x branch: depthwise 3x3 + bias + silu ----------------
__global__ void dw3_silu_kernel(const float* __restrict__ W, const float* __restrict__ bias)
{
    __shared__ float sm[66 * 68];
    int c = blockIdx.x;
    int b = blockIdx.y;
    int tid = threadIdx.x;
    const float* src = g_xz + ((long)b * 384 + c) * LQ;
    for (int e = tid; e < 66 * 68; e += 256) sm[e] = 0.f;
    __syncthreads();
    for (int e = tid; e < LQ; e += 256) {
        int h = e >> 6, w = e & 63;
        sm[(h + 1) * 68 + (w + 1)] = src[e];
    }
    __syncthreads();
    float w0 = W[c*9+0], w1 = W[c*9+1], w2 = W[c*9+2];
    float w3 = W[c*9+3], w4 = W[c*9+4], w5 = W[c*9+5];
    float w6 = W[c*9+6], w7 = W[c*9+7], w8 = W[c*9+8];
    float bb = bias[c];
    float* dst = g_xc + ((long)b * 192 + c) * LQ;
    for (int e = tid; e < LQ; e += 256) {
        int h = e >> 6, w = e & 63;
        const float* r0 = sm + h * 68 + w;
        float acc = bb + r0[0]*w0 + r0[1]*w1 + r0[2]*w2
                       + r0[68]*w3 + r0[69]*w4 + r0[70]*w5
                       + r0[136]*w6 + r0[137]*w7 + r0[138]*w8;
        dst[e] = acc / (1.f + __expf(-acc));
    }
}

// ---------------- haar 1x1 conv + strided combine -> yL, y_mean ----------------
__global__ void haar_kernel(const float* __restrict__ Wh)
{
    extern __shared__ float smh[];
    float* sW = smh;
    float* s1 = smh + 32 * 192;
    float* s2 = s1 + 192 * 32;
    int i = blockIdx.x, b = blockIdx.y;
    int tid = threadIdx.x;
    for (int e = tid; e < 32 * 192; e += 256) sW[e] = Wh[e];
    const float* xcb = g_xc + (long)b * 192 * LQ;
    for (int e = tid; e < 192 * 32; e += 256) {
        int d = e >> 5, j = e & 31;
        const float* row0 = xcb + (long)d * LQ + (2 * i) * 64 + 2 * j;
        float xa = row0[0], xb = row0[1];
        float xc2 = row0[64], xd = row0[65];
        s1[d * 32 + j] = xa + xb + xc2 + xd;
        s2[d * 32 + j] = 3.f * xa - xb - xc2 - xd;
    }
    __syncthreads();
    for (int e = tid; e < 2048; e += 256) {
        int which = e >> 10;
        int ch = (e >> 5) & 31;
        int j = e & 31;
        const float* sv = (which ? s2 : s1) + j;
        const float* wr = sW + ch * 192;
        float acc = 0.f;
#pragma unroll 4
        for (int d = 0; d < 192; d++) acc += wr[d] * sv[d * 32];
        acc *= which ? (1.f / 6.f) : 0.5f;
        int n = ch >> 2;
        int lpos = (ch & 3) * 1024 + i * 32 + j;
        float* dst = which ? g_ym : g_yL;
        dst[((long)b * 8 + n) * LQ + lpos] = acc;
    }
}

// ---------------- fused: conv1d(k=7) + dt projection + softplus + B/C assembly --------
__global__ void convdtbc_kernel(const float* __restrict__ Wx, const float* __restrict__ bx,
                                const float* __restrict__ Wdt, const float* __restrict__ dtb)
{
    __shared__ float sIn[22][264];
    __shared__ float sWd[192 * 6];
    __shared__ float sBd[192];
    __shared__ float sWc[22 * 7];
    __shared__ float sbc[22];
    int tid = threadIdx.x;
    int l0 = blockIdx.x * 256;
    int b = blockIdx.y;

    for (int e = tid; e < 1152; e += 256) sWd[e] = Wdt[e];
    for (int e = tid; e < 192; e += 256) sBd[e] = dtb[e];
    for (int e = tid; e < 154; e += 256) sWc[e] = Wx[e];
    for (int e = tid; e < 22; e += 256) sbc[e] = bx[e];
    for (int e = tid; e < 22 * 262; e += 256) {
        int c = e / 262, p = e % 262;
        int l = l0 + p - 3;
        float v = 0.f;
        if ((unsigned)l < (unsigned)LQ) v = g_xdbl[((long)b * 22 + c) * LQ + l];
        sIn[c][p] = v;
    }
    __syncthreads();

    int l = l0 + tid;
    float r[22];
#pragma unroll
    for (int c = 0; c < 22; c++) {
        float acc = sbc[c];
#pragma unroll
        for (int k = 0; k < 7; k++) acc += sIn[c][tid + k] * sWc[c * 7 + k];
        r[c] = acc;
    }
    float* dout = g_delta + (long)b * 192 * LQ + l;
    for (int d = 0; d < 192; d++) {
        float s = sBd[d];
#pragma unroll
        for (int rr = 0; rr < 6; rr++) s += sWd[d * 6 + rr] * r[rr];
        float sp = (s > 20.f) ? s : log1pf(expf(s));
        dout[(long)d * LQ] = sp;
    }
    float* o = g_BC + ((long)b * LQ + l) * 16;
    float bs[8], cs[8];
#pragma unroll
    for (int n = 0; n < 8; n++) {
        bs[n] = r[6 + n]  * g_yL[((long)b * 8 + n) * LQ + l] + 1e-6f;
        cs[n] = r[14 + n] * g_ym[((long)b * 8 + n) * LQ + l] + 1e-6f;
    }
    ((float4*)o)[0] = make_float4(bs[0], bs[1], bs[2], bs[3]);
    ((float4*)o)[1] = make_float4(bs[4], bs[5], bs[6], bs[7]);
    ((float4*)o)[2] = make_float4(cs[0], cs[1], cs[2], cs[3]);
    ((float4*)o)[3] = make_float4(cs[4], cs[5], cs[6], cs[7]);
}

// ---------------- selective scan ----------------
// exp reduction: when A[d][n] = A[d][0]*(n+1) (verified by prep2), p_n = q^(n+1)
// with q = exp(delta*A0): 1 MUFU + 7 FMUL instead of 8 MUFU per element.
__device__ __forceinline__ void make_powers(float q, float* p)
{
    float q2 = q * q;
    float q4 = q2 * q2;
    p[0] = q;       p[1] = q2;      p[2] = q2 * q;  p[3] = q4;
    p[4] = q4 * q;  p[5] = q4 * q2; p[6] = p[5] * q; p[7] = q4 * q4;
}

__global__ void scan_kernel(const float* __restrict__ Ds)
{
    extern __shared__ float sm[];
    float* sDelta = sm;
    float* sU = sm + 4096;
    float* sScan = sm + 8192;
    int bd = blockIdx.x;
    int b = bd / 192, d = bd % 192;
    int tid = threadIdx.x;
    const float* dp = g_delta + ((long)b * 192 + d) * LQ;
    const float* up = g_xc    + ((long)b * 192 + d) * LQ;
    for (int e = tid; e < LQ; e += 256) { sDelta[e] = dp[e]; sU[e] = up[e]; }
    float An[8];
#pragma unroll
    for (int n = 0; n < 8; n++) An[n] = g_A[d * 8 + n];
    bool powok = (g_pow_ok != 0);
    __syncthreads();
    const float* bc = g_BC + (long)b * LQ * 16;

    float a[8], hh[8];
#pragma unroll
    for (int n = 0; n < 8; n++) { a[n] = 1.f; hh[n] = 0.f; }
    int base = tid * 16;
    for (int i = 0; i < 16; i++) {
        int l = base + i;
        float delta = sDelta[l];
        float du = delta * sU[l];
        const float4* bc4 = (const float4*)(bc + (long)l * 16);
        float4 b0 = bc4[0], b1 = bc4[1];
        float bl[8] = {b0.x,b0.y,b0.z,b0.w,b1.x,b1.y,b1.z,b1.w};
        float p[8];
        if (powok) {
            make_powers(__expf(delta * An[0]), p);
        } else {
#pragma unroll
            for (int n = 0; n < 8; n++) p[n] = __expf(delta * An[n]);
        }
#pragma unroll
        for (int n = 0; n < 8; n++) {
            hh[n] = p[n] * hh[n] + du * bl[n];
            a[n] *= p[n];
        }
    }
#pragma unroll
    for (int n = 0; n < 8; n++) { sScan[n * 256 + tid] = a[n]; sScan[2048 + n * 256 + tid] = hh[n]; }
    __syncthreads();

    for (int off = 1; off < 256; off <<= 1) {
        float pa[8], pb[8];
        if (tid >= off) {
#pragma unroll
            for (int n = 0; n < 8; n++) {
                pa[n] = sScan[n * 256 + tid - off];
                pb[n] = sScan[2048 + n * 256 + tid - off];
            }
        }
        __syncthreads();
        if (tid >= off) {
#pragma unroll
            for (int n = 0; n < 8; n++) {
                float a2 = sScan[n * 256 + tid];
                float b2 = sScan[2048 + n * 256 + tid];
                sScan[n * 256 + tid] = pa[n] * a2;
                sScan[2048 + n * 256 + tid] = a2 * pb[n] + b2;
            }
        }
        __syncthreads();
    }
    float h0[8];
#pragma unroll
    for (int n = 0; n < 8; n++) h0[n] = (tid == 0) ? 0.f : sScan[2048 + n * 256 + tid - 1];
    __syncthreads();

    float Dd = Ds[d];
    for (int i = 0; i < 16; i++) {
        int l = base + i;
        float delta = sDelta[l];
        float u = sU[l];
        float du = delta * u;
        const float4* bc4 = (const float4*)(bc + (long)l * 16);
        float4 b0 = bc4[0], b1 = bc4[1], c0 = bc4[2], c1 = bc4[3];
        float bl[8] = {b0.x,b0.y,b0.z,b0.w,b1.x,b1.y,b1.z,b1.w};
        float cl[8] = {c0.x,c0.y,c0.z,c0.w,c1.x,c1.y,c1.z,c1.w};
        float p[8];
        if (powok) {
            make_powers(__expf(delta * An[0]), p);
        } else {
#pragma unroll
            for (int n = 0; n < 8; n++) p[n] = __expf(delta * An[n]);
        }
        float y = Dd * u;
#pragma unroll
        for (int n = 0; n < 8; n++) {
            h0[n] = p[n] * h0[n] + du * bl[n];
            y += h0[n] * cl[n];
        }
        sScan[l] = y;
    }
    __syncthreads();
    float* yo = g_y + ((long)b * 192 + d) * LQ;
    for (int e = tid; e < LQ; e += 256) yo[e] = sScan[e];
}

// ---------------- LayerNorm + silu(z) gate ----------------
__global__ void ln_kernel(const float* __restrict__ gamma, const float* __restrict__ beta)
{
    __shared__ float sg[192], sb2[192];
    int tid = threadIdx.x;
    for (int e = tid; e < 192; e += 256) { sg[e] = gamma[e]; sb2[e] = beta[e]; }
    __syncthreads();
    int l = blockIdx.x * 256 + tid;
    int b = blockIdx.y;
    const float* yp = g_y + (long)b * 192 * LQ + l;
    float s = 0.f, ss = 0.f;
    for (int dd = 0; dd < 192; dd++) {
        float v = yp[(long)dd * LQ];
        s += v; ss += v * v;
    }
    float mu = s * (1.f / 192.f);
    float var = ss * (1.f / 192.f) - mu * mu;
    float rs = rsqrtf(var + 1e-5f);
    const float* zp = g_zsil + (long)b * 192 * LQ + l;
    float* op = g_yn + (long)b * 192 * LQ + l;
    for (int dd = 0; dd < 192; dd++) {
        float v = (yp[(long)dd * LQ] - mu) * rs * sg[dd] + sb2[dd];
        op[(long)dd * LQ] = v * zp[(long)dd * LQ];
    }
}

// ---------------- host launcher ----------------
extern "C" void kernel_launch(void* const* d_in, const int* in_sizes, int n_in,
                              void* d_out, int out_size)
{
    const float* x        = (const float*)d_in[0];
    const float* W_in     = (const float*)d_in[1];
    const float* W_dwc_i  = (const float*)d_in[2];
    const float* b_dwc_i  = (const float*)d_in[3];
    const float* W_dw3    = (const float*)d_in[4];
    const float* b_dw3    = (const float*)d_in[5];
    const float* W_dw5    = (const float*)d_in[6];
    const float* b_dw5    = (const float*)d_in[7];
    const float* W_dw7    = (const float*)d_in[8];
    const float* b_dw7    = (const float*)d_in[9];
    const float* W_dwc_f  = (const float*)d_in[10];
    const float* b_dwc_f  = (const float*)d_in[11];
    const float* W_conv2d = (const float*)d_in[12];
    const float* b_conv2d = (const float*)d_in[13];
    const float* W_haar   = (const float*)d_in[14];
    const float* x_proj_w = (const float*)d_in[15];
    const float* W_xconv  = (const float*)d_in[16];
    const float* b_xconv  = (const float*)d_in[17];
    const float* dt_w     = (const float*)d_in[18];
    const float* dt_b     = (const float*)d_in[19];
    const float* A_logs   = (const float*)d_in[20];
    const float* Ds       = (const float*)d_in[21];
    const float* ln_g     = (const float*)d_in[22];
    const float* ln_b     = (const float*)d_in[23];
    const float* W_out    = (const float*)d_in[24];
    float* out = (float*)d_out;

    float *p_xz, *p_t, *p_t2, *p_zsil, *p_xc, *p_xdbl, *p_yn;
    cudaGetSymbolAddress((void**)&p_xz, g_xz);
    cudaGetSymbolAddress((void**)&p_t, g_t);
    cudaGetSymbolAddress((void**)&p_t2, g_t2);
    cudaGetSymbolAddress((void**)&p_zsil, g_zsil);
    cudaGetSymbolAddress((void**)&p_xc, g_xc);
    cudaGetSymbolAddress((void**)&p_xdbl, g_xdbl);
    cudaGetSymbolAddress((void**)&p_yn, g_yn);

    const int SMEM_SPLIT = (2*64*36 + 2*32*136) * 4;
    const int SMEM_PLAIN = (64*36 + 32*136) * 4;
    cudaFuncSetAttribute((const void*)gemm_tf32_kernel<true, 0>,
                         cudaFuncAttributeMaxDynamicSharedMemorySize, SMEM_SPLIT);
    cudaFuncSetAttribute((const void*)gemm_tf32_kernel<false, 1>,
                         cudaFuncAttributeMaxDynamicSharedMemorySize, SMEM_PLAIN);
    cudaFuncSetAttribute((const void*)gemm_tf32_kernel<false, 2>,
                         cudaFuncAttributeMaxDynamicSharedMemorySize, SMEM_PLAIN);
    cudaFuncSetAttribute(haar_kernel, cudaFuncAttributeMaxDynamicSharedMemorySize, 73728);
    cudaFuncSetAttribute(scan_kernel, cudaFuncAttributeMaxDynamicSharedMemorySize, 49152);

    static cudaStream_t sZ = nullptr;
    static cudaEvent_t evFork = nullptr, evJoin = nullptr;
    if (!sZ) {
        cudaStreamCreateWithFlags(&sZ, cudaStreamNonBlocking);
        cudaEventCreateWithFlags(&evFork, cudaEventDisableTiming);
        cudaEventCreateWithFlags(&evJoin, cudaEventDisableTiming);
    }

    prep_kernel<<<6, 256>>>(A_logs);
    prep2_kernel<<<1, 256>>>();

    gemm_tf32_kernel<true, 0><<<dim3(32, 6, NB), 256, SMEM_SPLIT>>>(
        x, 96L * LQ, W_in, nullptr, p_xz, nullptr, 384L * LQ, 384, 96);

    // ---- fork: z branch on stream sZ ----
    cudaEventRecord(evFork, 0);
    cudaStreamWaitEvent(sZ, evFork, 0);

    gemm_tf32_kernel<false, 1><<<dim3(32, 6, NB), 256, SMEM_PLAIN, sZ>>>(
        p_xz + 192L * LQ, 384L * LQ, W_dwc_i, b_dwc_i, p_t, p_t2, 384L * LQ, 384, 192);
    dwconv_gelu_kernel<3><<<dim3(96, NB), 256, 0, sZ>>>(W_dw3, b_dw3, 96);
    dwconv_gelu_kernel<5><<<dim3(96, NB), 256, 0, sZ>>>(W_dw5, b_dw5, 192);
    dwconv_gelu_kernel<7><<<dim3(96, NB), 256, 0, sZ>>>(W_dw7, b_dw7, 288);
    gemm_tf32_kernel<false, 2><<<dim3(32, 3, NB), 256, SMEM_PLAIN, sZ>>>(
        p_t2, 384L * LQ, W_dwc_f, b_dwc_f, p_zsil, nullptr, 192L * LQ, 192, 384);
    cudaEventRecord(evJoin, sZ);

    // ---- x branch on default stream ----
    dw3_silu_kernel<<<dim3(192, NB), 256>>>(W_conv2d, b_conv2d);
    haar_kernel<<<dim3(32, NB), 256, 73728>>>(W_haar);
    gemm_tf32_kernel<true, 0><<<dim3(32, 1, NB), 256, SMEM_SPLIT>>>(
        p_xc, 192L * LQ, x_proj_w, nullptr, p_xdbl, nullptr, 22L * LQ, 22, 192);
    convdtbc_kernel<<<dim3(16, NB), 256>>>(W_xconv, b_xconv, dt_w, dt_b);
    scan_kernel<<<NB * 192, 256, 49152>>>(Ds);

    // ---- join, then LN + output GEMM ----
    cudaStreamWaitEvent(0, evJoin, 0);
    ln_kernel<<<dim3(16, NB), 256>>>(ln_g, ln_b);
    gemm_tf32_kernel<true, 0><<<dim3(32, 2, NB), 256, SMEM_SPLIT>>>(
        p_yn, 192L * LQ, W_out, nullptr, out, nullptr, 96L * LQ, 96, 192);
    (void)in_sizes; (void)n_in; (void)out_size;
}